// round 14
// baseline (speedup 1.0000x reference)
#include <cuda_runtime.h>
#include <cuda_fp16.h>
#include <math.h>
#include <stdint.h>

#define BATCH 2
#define TLEN 2048
#define MLEN 77
#define CDIM 512
#define HEADS 8
#define BT 4096
#define NBIG 2097152
#define NSMALL 78848
#define MSMALL 154
#define WTSZ 262144
#define QSCALE 0.18033688011112042f   // 0.125 * log2(e)
#define NEGB (-30000.0f)
#define NSPLIT 4

// fp16 scratch: XH,Q,K,V,Y,YC,G1,G2,F (9*NBIG), CH,KC,VC (3*NSMALL), WT[8]
__device__ __half g_h[9ULL * NBIG + 3ULL * NSMALL + 8ULL * WTSZ];
// split-KV partials: unnormalized O (fp16) for NSPLIT quarters + per-row (m,l) fp32
__device__ __half g_po[(size_t)NSPLIT * NBIG];
__device__ float2 g_ml[(size_t)NSPLIT * BT * HEADS];

// ---------------------------------------------------------------------------
// helpers
// ---------------------------------------------------------------------------
__device__ __forceinline__ uint32_t smem_u32(const void* p) {
    return (uint32_t)__cvta_generic_to_shared(p);
}
__device__ __forceinline__ void ldsm_x4(uint32_t& r0, uint32_t& r1,
                                        uint32_t& r2, uint32_t& r3, uint32_t a) {
    asm volatile("ldmatrix.sync.aligned.m8n8.x4.shared.b16 {%0,%1,%2,%3}, [%4];"
                 : "=r"(r0), "=r"(r1), "=r"(r2), "=r"(r3) : "r"(a));
}
__device__ __forceinline__ void ldsm_x4_t(uint32_t& r0, uint32_t& r1,
                                          uint32_t& r2, uint32_t& r3, uint32_t a) {
    asm volatile("ldmatrix.sync.aligned.m8n8.x4.trans.shared.b16 {%0,%1,%2,%3}, [%4];"
                 : "=r"(r0), "=r"(r1), "=r"(r2), "=r"(r3) : "r"(a));
}
__device__ __forceinline__ void mma16816(float (&d)[4],
    uint32_t a0, uint32_t a1, uint32_t a2, uint32_t a3, uint32_t b0, uint32_t b1) {
    asm volatile(
        "mma.sync.aligned.m16n8k16.row.col.f32.f16.f16.f32 "
        "{%0,%1,%2,%3}, {%4,%5,%6,%7}, {%8,%9}, {%0,%1,%2,%3};\n"
        : "+f"(d[0]), "+f"(d[1]), "+f"(d[2]), "+f"(d[3])
        : "r"(a0), "r"(a1), "r"(a2), "r"(a3), "r"(b0), "r"(b1));
}
__device__ __forceinline__ float ex2(float x) {
    float r;
    asm("ex2.approx.ftz.f32 %0, %1;" : "=f"(r) : "f"(x));
    return r;
}
__device__ __forceinline__ float sigf(float x) {
    return 1.f / (1.f + __expf(-x));
}
__device__ __forceinline__ void cp16(uint32_t s, const void* g) {
    asm volatile("cp.async.cg.shared.global [%0], [%1], 16;" :: "r"(s), "l"(g));
}
__device__ __forceinline__ void cp_commit() {
    asm volatile("cp.async.commit_group;");
}
template <int N>
__device__ __forceinline__ void cp_wait() {
    asm volatile("cp.async.wait_group %0;" :: "n"(N));
}

// ---------------------------------------------------------------------------
// merged prep: blocks [0, NCONV) convert x,c -> fp16;
//              blocks [NCONV, NCONV+2048) transpose 8 weights -> fp16 [n][k]
// ---------------------------------------------------------------------------
#define NCONV ((NBIG / 8 + NSMALL / 8 + 255) / 256)   // 1063

__global__ __launch_bounds__(256) void prep_kernel(
    const float* __restrict__ x, const float* __restrict__ c,
    const float* __restrict__ W0, const float* __restrict__ W1,
    const float* __restrict__ W2, const float* __restrict__ W3,
    const float* __restrict__ W4, const float* __restrict__ W5,
    const float* __restrict__ W6, const float* __restrict__ W7,
    __half* __restrict__ xh, __half* __restrict__ ch, __half* __restrict__ Wt)
{
    const int bid = blockIdx.x;
    const int tid = threadIdx.x;
    if (bid < NCONV) {
        const int i = bid * 256 + tid;
        const float* src;
        __half* dst;
        int k;
        if (i < NBIG / 8) { src = x; dst = xh; k = i; }
        else if (i < (NBIG + NSMALL) / 8) { src = c; dst = ch; k = i - NBIG / 8; }
        else return;
        const float4 f0 = reinterpret_cast<const float4*>(src)[k * 2];
        const float4 f1 = reinterpret_cast<const float4*>(src)[k * 2 + 1];
        __half2 hh[4];
        hh[0] = __floats2half2_rn(f0.x, f0.y);
        hh[1] = __floats2half2_rn(f0.z, f0.w);
        hh[2] = __floats2half2_rn(f1.x, f1.y);
        hh[3] = __floats2half2_rn(f1.z, f1.w);
        reinterpret_cast<uint4*>(dst)[k] = *reinterpret_cast<uint4*>(hh);
    } else {
        __shared__ __half t[32][33];
        const int r = bid - NCONV;
        const int z = r >> 8;
        const int by = (r >> 4) & 15;
        const int bx = r & 15;
        const float* src = (z == 0) ? W0 : (z == 1) ? W1 : (z == 2) ? W2 : (z == 3) ? W3
                         : (z == 4) ? W4 : (z == 5) ? W5 : (z == 6) ? W6 : W7;
        __half* dst = Wt + (size_t)z * WTSZ;
        const int tx = tid & 31, ty = tid >> 5;
        const int k0 = by * 32, n0 = bx * 32;
#pragma unroll
        for (int i = 0; i < 4; ++i)
            t[ty + i * 8][tx] = __float2half_rn(src[(size_t)(k0 + ty + i * 8) * 512 + n0 + tx]);
        __syncthreads();
#pragma unroll
        for (int i = 0; i < 4; ++i)
            dst[(size_t)(n0 + ty + i * 8) * 512 + k0 + tx] = t[tx][ty + i * 8];
    }
}

// ---------------------------------------------------------------------------
// fp16 GEMM core (128x128, register-double-buffered — measured best, frozen)
// ---------------------------------------------------------------------------
__device__ __forceinline__ void gemm_core(
    const __half* __restrict__ A, const __half* __restrict__ Wt,
    const float* __restrict__ bias,
    __half* __restrict__ outh, float* __restrict__ outf, float oscale,
    int Mrows, int m0, int n0)
{
    __shared__ __half sA[2][128][40];
    __shared__ __half sB[2][128][40];

    const int tid = threadIdx.x;
    const int lane = tid & 31;
    const int wid = tid >> 5;
    const int wm = (wid >> 1) * 32;
    const int wn = (wid & 1) * 64;
    const int g = lane >> 2;
    const int tg = lane & 3;

    const int ar = tid >> 1;
    const int ak = (tid & 1) * 16;
    const bool aok = (m0 + ar) < Mrows;
    const __half* aptr = A + (size_t)(m0 + ar) * 512 + ak;
    const __half* bptr = Wt + (size_t)(n0 + ar) * 512 + ak;

    const int arow = wm + (lane & 15);
    const int acol = (lane >> 4) * 8;
    const int brow = wn + ((lane >> 3) & 1) * 8 + (lane & 7);
    const int bcol = (lane >> 4) * 8;

    float acc[2][8][4];
#pragma unroll
    for (int im = 0; im < 2; ++im)
#pragma unroll
        for (int in = 0; in < 8; ++in)
#pragma unroll
            for (int j = 0; j < 4; ++j) acc[im][in][j] = 0.f;

    uint4 ra0, ra1, rb0, rb1;
    const uint4 z4 = make_uint4(0, 0, 0, 0);

    auto load_stage = [&](int k0) {
        ra0 = aok ? *reinterpret_cast<const uint4*>(aptr + k0) : z4;
        ra1 = aok ? *reinterpret_cast<const uint4*>(aptr + k0 + 8) : z4;
        rb0 = *reinterpret_cast<const uint4*>(bptr + k0);
        rb1 = *reinterpret_cast<const uint4*>(bptr + k0 + 8);
    };
    auto store_stage = [&](int buf) {
        *reinterpret_cast<uint4*>(&sA[buf][ar][ak]) = ra0;
        *reinterpret_cast<uint4*>(&sA[buf][ar][ak + 8]) = ra1;
        *reinterpret_cast<uint4*>(&sB[buf][ar][ak]) = rb0;
        *reinterpret_cast<uint4*>(&sB[buf][ar][ak + 8]) = rb1;
    };

    load_stage(0);
    store_stage(0);
    __syncthreads();

#pragma unroll 1
    for (int it = 0; it < 16; ++it) {
        const int buf = it & 1;
        if (it < 15) load_stage((it + 1) * 32);

#pragma unroll
        for (int kc = 0; kc < 32; kc += 16) {
            uint32_t a[2][4];
#pragma unroll
            for (int im = 0; im < 2; ++im)
                ldsm_x4(a[im][0], a[im][1], a[im][2], a[im][3],
                        smem_u32(&sA[buf][arow + im * 16][acol + kc]));
#pragma unroll
            for (int nq = 0; nq < 4; ++nq) {
                uint32_t b0, b1, b2, b3;
                ldsm_x4(b0, b1, b2, b3,
                        smem_u32(&sB[buf][brow + nq * 16][bcol + kc]));
#pragma unroll
                for (int im = 0; im < 2; ++im) {
                    mma16816(acc[im][2 * nq],     a[im][0], a[im][1], a[im][2], a[im][3], b0, b2);
                    mma16816(acc[im][2 * nq + 1], a[im][0], a[im][1], a[im][2], a[im][3], b1, b3);
                }
            }
        }
        if (it < 15) {
            store_stage(1 - buf);
            __syncthreads();
        }
    }

#pragma unroll
    for (int in = 0; in < 8; ++in) {
        const int col = n0 + wn + in * 8 + tg * 2;
        const float2 bb = *reinterpret_cast<const float2*>(bias + col);
#pragma unroll
        for (int im = 0; im < 2; ++im) {
            const int r0 = m0 + wm + im * 16 + g;
            const int r1 = r0 + 8;
            if (r0 < Mrows) {
                const float v0 = (acc[im][in][0] + bb.x) * oscale;
                const float v1 = (acc[im][in][1] + bb.y) * oscale;
                if (outh)
                    *reinterpret_cast<__half2*>(outh + (size_t)r0 * 512 + col) =
                        __floats2half2_rn(v0, v1);
                else
                    *reinterpret_cast<float2*>(outf + (size_t)r0 * 512 + col) =
                        make_float2(v0, v1);
            }
            if (r1 < Mrows) {
                const float v2 = (acc[im][in][2] + bb.x) * oscale;
                const float v3 = (acc[im][in][3] + bb.y) * oscale;
                if (outh)
                    *reinterpret_cast<__half2*>(outh + (size_t)r1 * 512 + col) =
                        __floats2half2_rn(v2, v3);
                else
                    *reinterpret_cast<float2*>(outf + (size_t)r1 * 512 + col) =
                        make_float2(v2, v3);
            }
        }
    }
}

// projections: Q(pre-scaled),K,V (3x128) + KC,VC (2x8) = 400 blocks
__global__ __launch_bounds__(256) void proj_kernel(
    const __half* __restrict__ xh, const __half* __restrict__ ch,
    const __half* __restrict__ Wt,
    const float* __restrict__ bq, const float* __restrict__ bk,
    const float* __restrict__ bv, const float* __restrict__ bkc,
    const float* __restrict__ bvc,
    __half* __restrict__ Qh, __half* __restrict__ Kh, __half* __restrict__ Vh,
    __half* __restrict__ KCh, __half* __restrict__ VCh)
{
    const int bid = blockIdx.x;
    const __half *A, *W;
    const float* bias;
    __half* out;
    float oscale = 1.0f;
    int Mrows, m0, n0;
    if (bid < 384) {
        const int t = bid / 128, l = bid % 128;
        m0 = (l >> 2) * 128;
        n0 = (l & 3) * 128;
        A = xh; Mrows = BT;
        W = Wt + (size_t)t * WTSZ;
        bias = (t == 0) ? bq : ((t == 1) ? bk : bv);
        out = (t == 0) ? Qh : ((t == 1) ? Kh : Vh);
        if (t == 0) oscale = QSCALE;
    } else {
        const int r = bid - 384;
        const int t = r / 8, l = r % 8;
        m0 = (l >> 2) * 128;
        n0 = (l & 3) * 128;
        A = ch; Mrows = MSMALL;
        W = Wt + (size_t)(3 + t) * WTSZ;
        bias = t ? bvc : bkc;
        out = t ? VCh : KCh;
    }
    gemm_core(A, W, bias, out, nullptr, oscale, Mrows, m0, n0);
}

__global__ __launch_bounds__(256) void gates_kernel(
    const __half* __restrict__ Yh, const __half* __restrict__ YCh,
    const __half* __restrict__ Wt,
    const float* __restrict__ bg1, const float* __restrict__ bg2,
    __half* __restrict__ G1, __half* __restrict__ G2)
{
    const int bid = blockIdx.x;
    const int t = bid >> 7;
    const int l = bid & 127;
    gemm_core(t ? YCh : Yh, Wt + (size_t)(5 + t) * WTSZ, t ? bg2 : bg1,
              t ? G2 : G1, nullptr, 1.0f, BT, (l >> 2) * 128, (l & 3) * 128);
}

__global__ __launch_bounds__(256) void final_gemm_kernel(
    const __half* __restrict__ F, const __half* __restrict__ Wt,
    const float* __restrict__ bp, float* __restrict__ out)
{
    const int l = blockIdx.x;
    gemm_core(F, Wt + 7ULL * WTSZ, bp, nullptr, out, 1.0f, BT,
              (l >> 2) * 128, (l & 3) * 128);
}

// ---------------------------------------------------------------------------
// Attention kernel, 4-way split-KV self-attention + cross. grid (80, B*H).
// Single __syncthreads per key tile. Partials stored in fp16.
// ---------------------------------------------------------------------------
#define SAS 72
#define CPS 88

__global__ __launch_bounds__(256, 3) void attn_kernel(
    const __half* __restrict__ Q, const __half* __restrict__ K,
    const __half* __restrict__ V,
    const __half* __restrict__ Kc, const __half* __restrict__ Vc,
    const int* __restrict__ pad,
    __half* __restrict__ po, float2* __restrict__ ml,
    __half* __restrict__ Yc)
{
    extern __shared__ __half smh[];

    const int bh = blockIdx.y;
    const int b = bh >> 3;
    const int h = bh & 7;
    const int tid = threadIdx.x;
    const int lane = tid & 31;
    const int wid = tid >> 5;
    const int g = lane >> 2;
    const int tg = lane & 3;
    const int wm = wid * 16;

    const size_t qbase = ((size_t)b * TLEN) * CDIM + h * 64;

    const int arow = wm + (lane & 15);
    const int acol = (lane >> 4) * 8;
    const int brow = ((lane >> 3) & 1) * 8 + (lane & 7);
    const int bcol = (lane >> 4) * 8;
    const int vrow = (lane & 7) + ((lane >> 4) & 1) * 8;
    const int vcol = ((lane >> 3) & 1) * 8;
    const int rA = wm + g;

    if (blockIdx.x < 64) {
        // ============ causal self-attention (split-KV quarter) ============
        __half* sQ = smh;                     // [128][72]
        __half* sP = sQ + 128 * SAS;          // [128][72]
        __half* sK = sP + 128 * SAS;          // [2][64][72]
        __half* sV = sK + 2 * 64 * SAS;       // [2][64][72]

        const int p = (int)blockIdx.x;
        const int qb = 15 - (p >> 2);
        const int quarter = p & 3;
        const int total = 2 * (qb + 1);
        const int jt0 = (total * quarter) >> 2;
        const int jtEnd = (total * (quarter + 1)) >> 2;
        const int nT = jtEnd - jt0;

        {
            const int r = tid >> 1, cb = (tid & 1) * 32;
            const uint4* src = reinterpret_cast<const uint4*>(
                Q + qbase + (size_t)(qb * 128 + r) * CDIM + cb);
            uint4* dst = reinterpret_cast<uint4*>(&sQ[r * SAS + cb]);
            dst[0] = src[0]; dst[1] = src[1]; dst[2] = src[2]; dst[3] = src[3];
        }

        const int kvr = tid >> 2, kvc = (tid & 3) * 16;

        auto prefetch = [&](int jt, int buf) {
            const size_t gofs = qbase + (size_t)(jt * 64 + kvr) * CDIM + kvc;
            const uint32_t kd = smem_u32(&sK[(buf * 64 + kvr) * SAS + kvc]);
            const uint32_t vd = smem_u32(&sV[(buf * 64 + kvr) * SAS + kvc]);
            cp16(kd, K + gofs);
            cp16(kd + 16, K + gofs + 8);
            cp16(vd, V + gofs);
            cp16(vd + 16, V + gofs + 8);
        };

        float o[8][4];
#pragma unroll
        for (int in = 0; in < 8; ++in)
#pragma unroll
            for (int j = 0; j < 4; ++j) o[in][j] = 0.f;
        float mrow[2] = {NEGB, NEGB};
        float lrow[2] = {0.f, 0.f};

        const int qrA = qb * 128 + rA;
        const int qrB = qrA + 8;

        if (nT > 0) {
            prefetch(jt0, 0);
            cp_commit();

#pragma unroll 1
            for (int t = 0; t < nT; ++t) {
                const int jt = jt0 + t;
                const int buf = t & 1;
                cp_wait<0>();
                __syncthreads();
                if (t + 1 < nT) {
                    prefetch(jt + 1, buf ^ 1);
                    cp_commit();
                }

                float s[8][4];
#pragma unroll
                for (int in = 0; in < 8; ++in)
#pragma unroll
                    for (int j = 0; j < 4; ++j) s[in][j] = 0.f;

#pragma unroll
                for (int kc = 0; kc < 64; kc += 16) {
                    uint32_t a0, a1, a2, a3;
                    ldsm_x4(a0, a1, a2, a3, smem_u32(&sQ[arow * SAS + acol + kc]));
#pragma unroll
                    for (int nq = 0; nq < 4; ++nq) {
                        uint32_t b0, b1, b2, b3;
                        ldsm_x4(b0, b1, b2, b3,
                                smem_u32(&sK[(buf * 64 + nq * 16 + brow) * SAS + bcol + kc]));
                        mma16816(s[2 * nq],     a0, a1, a2, a3, b0, b2);
                        mma16816(s[2 * nq + 1], a0, a1, a2, a3, b1, b3);
                    }
                }

                if (jt >= 2 * qb) {
#pragma unroll
                    for (int in = 0; in < 8; ++in) {
                        const int cj = jt * 64 + in * 8 + tg * 2;
                        if (cj     > qrA) s[in][0] = NEGB;
                        if (cj + 1 > qrA) s[in][1] = NEGB;
                        if (cj     > qrB) s[in][2] = NEGB;
                        if (cj + 1 > qrB) s[in][3] = NEGB;
                    }
                }

                float rmA = NEGB, rmB = NEGB;
#pragma unroll
                for (int in = 0; in < 8; ++in) {
                    rmA = fmaxf(rmA, fmaxf(s[in][0], s[in][1]));
                    rmB = fmaxf(rmB, fmaxf(s[in][2], s[in][3]));
                }
                rmA = fmaxf(rmA, __shfl_xor_sync(0xffffffffu, rmA, 1));
                rmA = fmaxf(rmA, __shfl_xor_sync(0xffffffffu, rmA, 2));
                rmB = fmaxf(rmB, __shfl_xor_sync(0xffffffffu, rmB, 1));
                rmB = fmaxf(rmB, __shfl_xor_sync(0xffffffffu, rmB, 2));

                const float mA = fmaxf(mrow[0], rmA);
                const float mB = fmaxf(mrow[1], rmB);
                const float cA = ex2(mrow[0] - mA);
                const float cB = ex2(mrow[1] - mB);

                float rsA = 0.f, rsB = 0.f;
#pragma unroll
                for (int in = 0; in < 8; ++in) {
                    const float p0 = ex2(s[in][0] - mA);
                    const float p1 = ex2(s[in][1] - mA);
                    const float p2 = ex2(s[in][2] - mB);
                    const float p3 = ex2(s[in][3] - mB);
                    rsA += p0 + p1;
                    rsB += p2 + p3;
                    const int col = in * 8 + tg * 2;
                    *reinterpret_cast<__half2*>(&sP[rA * SAS + col]) = __floats2half2_rn(p0, p1);
                    *reinterpret_cast<__half2*>(&sP[(rA + 8) * SAS + col]) = __floats2half2_rn(p2, p3);
                }
                rsA += __shfl_xor_sync(0xffffffffu, rsA, 1);
                rsA += __shfl_xor_sync(0xffffffffu, rsA, 2);
                rsB += __shfl_xor_sync(0xffffffffu, rsB, 1);
                rsB += __shfl_xor_sync(0xffffffffu, rsB, 2);

                lrow[0] = lrow[0] * cA + rsA;
                lrow[1] = lrow[1] * cB + rsB;
                mrow[0] = mA;
                mrow[1] = mB;

#pragma unroll
                for (int in = 0; in < 8; ++in) {
                    o[in][0] *= cA; o[in][1] *= cA;
                    o[in][2] *= cB; o[in][3] *= cB;
                }
                __syncwarp();

#pragma unroll
                for (int kc = 0; kc < 64; kc += 16) {
                    uint32_t a0, a1, a2, a3;
                    ldsm_x4(a0, a1, a2, a3, smem_u32(&sP[arow * SAS + acol + kc]));
#pragma unroll
                    for (int dq = 0; dq < 4; ++dq) {
                        uint32_t b0, b1, b2, b3;
                        ldsm_x4_t(b0, b1, b2, b3,
                                  smem_u32(&sV[(buf * 64 + kc + vrow) * SAS + dq * 16 + vcol]));
                        mma16816(o[2 * dq],     a0, a1, a2, a3, b0, b2);
                        mma16816(o[2 * dq + 1], a0, a1, a2, a3, b1, b3);
                    }
                }
            }
        }

        // write unnormalized partials (fp16) + per-row (m, l)
        const int rowgA = b * TLEN + qrA;
        const int rowgB = rowgA + 8;
        __half* poA = po + (size_t)quarter * NBIG + (size_t)rowgA * 512 + h * 64;
        __half* poB = po + (size_t)quarter * NBIG + (size_t)rowgB * 512 + h * 64;
#pragma unroll
        for (int in = 0; in < 8; ++in) {
            const int col = in * 8 + tg * 2;
            *reinterpret_cast<__half2*>(poA + col) = __floats2half2_rn(o[in][0], o[in][1]);
            *reinterpret_cast<__half2*>(poB + col) = __floats2half2_rn(o[in][2], o[in][3]);
        }
        if (tg == 0) {
            ml[(size_t)quarter * BT * HEADS + (size_t)rowgA * HEADS + h] =
                make_float2(mrow[0], lrow[0]);
            ml[(size_t)quarter * BT * HEADS + (size_t)rowgB * HEADS + h] =
                make_float2(mrow[1], lrow[1]);
        }
    } else {
        // =================== cross-attention (unchanged) ===================
        __half* sQ = smh;
        __half* sP = sQ + 128 * SAS;
        __half* sK = sP + 128 * CPS;
        __half* sV = sK + 80 * SAS;
        int* sF = (int*)(sV + 80 * SAS);

        const int qb = (int)blockIdx.x - 64;
        const size_t kbase = ((size_t)b * MLEN) * CDIM + h * 64;

        {
            const int r = tid >> 1, cb = (tid & 1) * 32;
            const uint4* src = reinterpret_cast<const uint4*>(
                Q + qbase + (size_t)(qb * 128 + r) * CDIM + cb);
            uint4* dst = reinterpret_cast<uint4*>(&sQ[r * SAS + cb]);
            dst[0] = src[0]; dst[1] = src[1]; dst[2] = src[2]; dst[3] = src[3];
        }
        {
            const int r = tid >> 1, cb = (tid & 1) * 32;
            if (r < 80) {
                uint4 kv0, kv1, kv2, kv3, vv0, vv1, vv2, vv3;
                if (r < MLEN) {
                    const uint4* ks = reinterpret_cast<const uint4*>(Kc + kbase + (size_t)r * CDIM + cb);
                    const uint4* vs = reinterpret_cast<const uint4*>(Vc + kbase + (size_t)r * CDIM + cb);
                    kv0 = ks[0]; kv1 = ks[1]; kv2 = ks[2]; kv3 = ks[3];
                    vv0 = vs[0]; vv1 = vs[1]; vv2 = vs[2]; vv3 = vs[3];
                } else {
                    kv0 = kv1 = kv2 = kv3 = make_uint4(0, 0, 0, 0);
                    vv0 = vv1 = vv2 = vv3 = kv0;
                }
                uint4* kd = reinterpret_cast<uint4*>(&sK[r * SAS + cb]);
                uint4* vd = reinterpret_cast<uint4*>(&sV[r * SAS + cb]);
                kd[0] = kv0; kd[1] = kv1; kd[2] = kv2; kd[3] = kv3;
                vd[0] = vv0; vd[1] = vv1; vd[2] = vv2; vd[3] = vv3;
            }
        }
        if (tid < 80) sF[tid] = (tid < MLEN) ? pad[b * MLEN + tid] : 0;
        __syncthreads();

        float s[10][4];
#pragma unroll
        for (int in = 0; in < 10; ++in)
#pragma unroll
            for (int j = 0; j < 4; ++j) s[in][j] = 0.f;

#pragma unroll
        for (int kc = 0; kc < 64; kc += 16) {
            uint32_t a0, a1, a2, a3;
            ldsm_x4(a0, a1, a2, a3, smem_u32(&sQ[arow * SAS + acol + kc]));
#pragma unroll
            for (int nq = 0; nq < 5; ++nq) {
                uint32_t b0, b1, b2, b3;
                ldsm_x4(b0, b1, b2, b3,
                        smem_u32(&sK[(nq * 16 + brow) * SAS + bcol + kc]));
                mma16816(s[2 * nq],     a0, a1, a2, a3, b0, b2);
                mma16816(s[2 * nq + 1], a0, a1, a2, a3, b1, b3);
            }
        }

#pragma unroll
        for (int in = 0; in < 10; ++in) {
            const int cj = in * 8 + tg * 2;
            if (sF[cj] == 0)     { s[in][0] = NEGB; s[in][2] = NEGB; }
            if (sF[cj + 1] == 0) { s[in][1] = NEGB; s[in][3] = NEGB; }
        }

        float rmA = NEGB, rmB = NEGB;
#pragma unroll
        for (int in = 0; in < 10; ++in) {
            rmA = fmaxf(rmA, fmaxf(s[in][0], s[in][1]));
            rmB = fmaxf(rmB, fmaxf(s[in][2], s[in][3]));
        }
        rmA = fmaxf(rmA, __shfl_xor_sync(0xffffffffu, rmA, 1));
        rmA = fmaxf(rmA, __shfl_xor_sync(0xffffffffu, rmA, 2));
        rmB = fmaxf(rmB, __shfl_xor_sync(0xffffffffu, rmB, 1));
        rmB = fmaxf(rmB, __shfl_xor_sync(0xffffffffu, rmB, 2));

        float rsA = 0.f, rsB = 0.f;
#pragma unroll
        for (int in = 0; in < 10; ++in) {
            const float p0 = ex2(s[in][0] - rmA);
            const float p1 = ex2(s[in][1] - rmA);
            const float p2 = ex2(s[in][2] - rmB);
            const float p3 = ex2(s[in][3] - rmB);
            rsA += p0 + p1;
            rsB += p2 + p3;
            const int col = in * 8 + tg * 2;
            *reinterpret_cast<__half2*>(&sP[rA * CPS + col]) = __floats2half2_rn(p0, p1);
            *reinterpret_cast<__half2*>(&sP[(rA + 8) * CPS + col]) = __floats2half2_rn(p2, p3);
        }
        rsA += __shfl_xor_sync(0xffffffffu, rsA, 1);
        rsA += __shfl_xor_sync(0xffffffffu, rsA, 2);
        rsB += __shfl_xor_sync(0xffffffffu, rsB, 1);
        rsB += __shfl_xor_sync(0xffffffffu, rsB, 2);
        __syncwarp();

        float o[8][4];
#pragma unroll
        for (int in = 0; in < 8; ++in)
#pragma unroll
            for (int j = 0; j < 4; ++j) o[in][j] = 0.f;

#pragma unroll
        for (int kc = 0; kc < 80; kc += 16) {
            uint32_t a0, a1, a2, a3;
            ldsm_x4(a0, a1, a2, a3, smem_u32(&sP[arow * CPS + acol + kc]));
#pragma unroll
            for (int dq = 0; dq < 4; ++dq) {
                uint32_t b0, b1, b2, b3;
                ldsm_x4_t(b0, b1, b2, b3,
                          smem_u32(&sV[(kc + vrow) * SAS + dq * 16 + vcol]));
                mma16816(o[2 * dq],     a0, a1, a2, a3, b0, b2);
                mma16816(o[2 * dq + 1], a0, a1, a2, a3, b1, b3);
            }
        }

        const float invA = (rsA > 0.f) ? (1.f / rsA) : 0.f;
        const float invB = (rsB > 0.f) ? (1.f / rsB) : 0.f;
        const int qrA = qb * 128 + rA;
        const int qrB = qrA + 8;
#pragma unroll
        for (int in = 0; in < 8; ++in) {
            const int col = in * 8 + tg * 2;
            *reinterpret_cast<__half2*>(Yc + qbase + (size_t)qrA * CDIM + col) =
                __floats2half2_rn(o[in][0] * invA, o[in][1] * invA);
            *reinterpret_cast<__half2*>(Yc + qbase + (size_t)qrB * CDIM + col) =
                __floats2half2_rn(o[in][2] * invB, o[in][3] * invB);
        }
    }
}

// ---------------------------------------------------------------------------
// merge 4 fp16 split-KV partials: Y = sum O_q*w_q / sum l_q*w_q
// one thread per 8 output columns. grid = BT*64/256 = 1024.
// ---------------------------------------------------------------------------
__global__ __launch_bounds__(256) void merge_kernel(
    const __half* __restrict__ po, const float2* __restrict__ ml,
    __half* __restrict__ Y)
{
    const int idx = blockIdx.x * 256 + threadIdx.x;
    const int r = idx >> 6;
    const int c8 = (idx & 63) * 8;
    const int h = c8 >> 6;

    float2 mlq[NSPLIT];
#pragma unroll
    for (int q = 0; q < NSPLIT; ++q)
        mlq[q] = ml[(size_t)q * BT * HEADS + (size_t)r * HEADS + h];

    float m = mlq[0].x;
#pragma unroll
    for (int q = 1; q < NSPLIT; ++q) m = fmaxf(m, mlq[q].x);

    float w[NSPLIT], denom = 0.f;
#pragma unroll
    for (int q = 0; q < NSPLIT; ++q) {
        w[q] = ex2(mlq[q].x - m);
        denom += mlq[q].y * w[q];
    }
    const float inv = 1.f / denom;

    const size_t o = (size_t)r * 512 + c8;
    float acc[8];
#pragma unroll
    for (int j = 0; j < 8; ++j) acc[j] = 0.f;
#pragma unroll
    for (int q = 0; q < NSPLIT; ++q) {
        const float a = w[q] * inv;
        const uint4 u = *reinterpret_cast<const uint4*>(po + (size_t)q * NBIG + o);
        const __half2* hx = reinterpret_cast<const __half2*>(&u);
#pragma unroll
        for (int k = 0; k < 4; ++k) {
            const float2 f = __half22float2(hx[k]);
            acc[2 * k]     += f.x * a;
            acc[2 * k + 1] += f.y * a;
        }
    }

    __half2 outv[4];
    outv[0] = __floats2half2_rn(acc[0], acc[1]);
    outv[1] = __floats2half2_rn(acc[2], acc[3]);
    outv[2] = __floats2half2_rn(acc[4], acc[5]);
    outv[3] = __floats2half2_rn(acc[6], acc[7]);
    *reinterpret_cast<uint4*>(Y + o) = *reinterpret_cast<uint4*>(outv);
}

// ---------------------------------------------------------------------------
// fused = sigmoid(g1) * yc + sigmoid(g2) * y  (fp16 in/out)
// ---------------------------------------------------------------------------
__global__ __launch_bounds__(256) void gate_fuse_kernel(
    const __half* __restrict__ g1, const __half* __restrict__ g2,
    const __half* __restrict__ y, const __half* __restrict__ yc,
    __half* __restrict__ f)
{
    const int i = blockIdx.x * 256 + threadIdx.x;
    const uint4 ua = reinterpret_cast<const uint4*>(g1)[i];
    const uint4 ub = reinterpret_cast<const uint4*>(g2)[i];
    const uint4 uy = reinterpret_cast<const uint4*>(y)[i];
    const uint4 uc = reinterpret_cast<const uint4*>(yc)[i];
    const __half2* ha = reinterpret_cast<const __half2*>(&ua);
    const __half2* hb = reinterpret_cast<const __half2*>(&ub);
    const __half2* hy = reinterpret_cast<const __half2*>(&uy);
    const __half2* hc = reinterpret_cast<const __half2*>(&uc);
    __half2 ho[4];
#pragma unroll
    for (int k = 0; k < 4; ++k) {
        const float2 a = __half22float2(ha[k]);
        const float2 bg = __half22float2(hb[k]);
        const float2 yv = __half22float2(hy[k]);
        const float2 yw = __half22float2(hc[k]);
        ho[k] = __floats2half2_rn(sigf(a.x) * yw.x + sigf(bg.x) * yv.x,
                                  sigf(a.y) * yw.y + sigf(bg.y) * yv.y);
    }
    reinterpret_cast<uint4*>(f)[i] = *reinterpret_cast<uint4*>(ho);
}

// ---------------------------------------------------------------------------
// Launch
// ---------------------------------------------------------------------------
extern "C" void kernel_launch(void* const* d_in, const int* in_sizes, int n_in,
                              void* d_out, int out_size)
{
    const float* x  = (const float*)d_in[0];
    const float* c  = (const float*)d_in[1];
    const int* pad  = (const int*)d_in[3];
    const float* Wq = (const float*)d_in[4];
    const float* bq = (const float*)d_in[5];
    const float* Wk = (const float*)d_in[6];
    const float* bk = (const float*)d_in[7];
    const float* Wv = (const float*)d_in[8];
    const float* bv = (const float*)d_in[9];
    const float* Wkc = (const float*)d_in[10];
    const float* bkc = (const float*)d_in[11];
    const float* Wvc = (const float*)d_in[12];
    const float* bvc = (const float*)d_in[13];
    const float* Wg1 = (const float*)d_in[14];
    const float* bg1 = (const float*)d_in[15];
    const float* Wg2 = (const float*)d_in[16];
    const float* bg2 = (const float*)d_in[17];
    const float* Wp = (const float*)d_in[18];
    const float* bp = (const float*)d_in[19];
    float* out = (float*)d_out;

    __half* H = nullptr;
    cudaGetSymbolAddress((void**)&H, g_h);
    __half* PO = nullptr;
    cudaGetSymbolAddress((void**)&PO, g_po);
    float2* ML = nullptr;
    cudaGetSymbolAddress((void**)&ML, g_ml);

    __half* XH  = H + 0ULL * NBIG;
    __half* Qh  = H + 1ULL * NBIG;
    __half* Kh  = H + 2ULL * NBIG;
    __half* Vh  = H + 3ULL * NBIG;
    __half* Yh  = H + 4ULL * NBIG;
    __half* YCh = H + 5ULL * NBIG;
    __half* G1h = H + 6ULL * NBIG;
    __half* G2h = H + 7ULL * NBIG;
    __half* Fh  = H + 8ULL * NBIG;
    __half* CH  = H + 9ULL * NBIG;
    __half* KCh = CH + NSMALL;
    __half* VCh = CH + 2ULL * NSMALL;
    __half* WT  = CH + 3ULL * NSMALL;

    const int SMEM_AT = (128 * SAS + 128 * SAS + 128 * SAS + 128 * SAS) * 2; // 73728
    cudaFuncSetAttribute(attn_kernel,
                         cudaFuncAttributeMaxDynamicSharedMemorySize, SMEM_AT);

    prep_kernel<<<NCONV + 2048, 256>>>(x, c, Wq, Wk, Wv, Wkc, Wvc, Wg1, Wg2, Wp,
                                       XH, CH, WT);

    proj_kernel<<<400, 256>>>(XH, CH, WT, bq, bk, bv, bkc, bvc,
                              Qh, Kh, Vh, KCh, VCh);

    attn_kernel<<<dim3(80, BATCH * HEADS), 256, SMEM_AT>>>(
        Qh, Kh, Vh, KCh, VCh, pad, PO, ML, YCh);
    merge_kernel<<<BT * 64 / 256, 256>>>(PO, ML, Yh);

    gates_kernel<<<256, 256>>>(Yh, YCh, WT, bg1, bg2, G1h, G2h);
    gate_fuse_kernel<<<NBIG / 8 / 256, 256>>>(G1h, G2h, Yh, YCh, Fh);
    final_gemm_kernel<<<128, 256>>>(Fh, WT, bp, out);
}

// round 15
// speedup vs baseline: 1.4818x; 1.4818x over previous
#include <cuda_runtime.h>
#include <cuda_fp16.h>
#include <math.h>
#include <stdint.h>

#define BATCH 2
#define TLEN 2048
#define MLEN 77
#define CDIM 512
#define HEADS 8
#define BT 4096
#define NBIG 2097152
#define NSMALL 78848
#define MSMALL 154
#define WTSZ 262144
#define QSCALE 0.18033688011112042f   // 0.125 * log2(e)
#define NEGB (-30000.0f)
#define NSPLIT 4

// fp16 scratch: XH,Q,K,V,Y,YC,G1,G2,F (9*NBIG), CH,KC,VC (3*NSMALL), WT[8]
__device__ __half g_h[9ULL * NBIG + 3ULL * NSMALL + 8ULL * WTSZ];
// split-KV partials: unnormalized O (fp32) for NSPLIT quarters + per-row (m,l)
__device__ float g_po[(size_t)NSPLIT * NBIG];
__device__ float2 g_ml[(size_t)NSPLIT * BT * HEADS];

// ---------------------------------------------------------------------------
// helpers
// ---------------------------------------------------------------------------
__device__ __forceinline__ uint32_t smem_u32(const void* p) {
    return (uint32_t)__cvta_generic_to_shared(p);
}
__device__ __forceinline__ void ldsm_x4(uint32_t& r0, uint32_t& r1,
                                        uint32_t& r2, uint32_t& r3, uint32_t a) {
    asm volatile("ldmatrix.sync.aligned.m8n8.x4.shared.b16 {%0,%1,%2,%3}, [%4];"
                 : "=r"(r0), "=r"(r1), "=r"(r2), "=r"(r3) : "r"(a));
}
__device__ __forceinline__ void ldsm_x4_t(uint32_t& r0, uint32_t& r1,
                                          uint32_t& r2, uint32_t& r3, uint32_t a) {
    asm volatile("ldmatrix.sync.aligned.m8n8.x4.trans.shared.b16 {%0,%1,%2,%3}, [%4];"
                 : "=r"(r0), "=r"(r1), "=r"(r2), "=r"(r3) : "r"(a));
}
__device__ __forceinline__ void mma16816(float (&d)[4],
    uint32_t a0, uint32_t a1, uint32_t a2, uint32_t a3, uint32_t b0, uint32_t b1) {
    asm volatile(
        "mma.sync.aligned.m16n8k16.row.col.f32.f16.f16.f32 "
        "{%0,%1,%2,%3}, {%4,%5,%6,%7}, {%8,%9}, {%0,%1,%2,%3};\n"
        : "+f"(d[0]), "+f"(d[1]), "+f"(d[2]), "+f"(d[3])
        : "r"(a0), "r"(a1), "r"(a2), "r"(a3), "r"(b0), "r"(b1));
}
__device__ __forceinline__ float ex2(float x) {
    float r;
    asm("ex2.approx.ftz.f32 %0, %1;" : "=f"(r) : "f"(x));
    return r;
}
__device__ __forceinline__ float sigf(float x) {
    return 1.f / (1.f + __expf(-x));
}
__device__ __forceinline__ void cp16(uint32_t s, const void* g) {
    asm volatile("cp.async.cg.shared.global [%0], [%1], 16;" :: "r"(s), "l"(g));
}
__device__ __forceinline__ void cp_commit() {
    asm volatile("cp.async.commit_group;");
}
template <int N>
__device__ __forceinline__ void cp_wait() {
    asm volatile("cp.async.wait_group %0;" :: "n"(N));
}

// ---------------------------------------------------------------------------
// merged prep: blocks [0, NCONV) convert x,c -> fp16;
//              blocks [NCONV, NCONV+2048) transpose 8 weights -> fp16 [n][k]
// ---------------------------------------------------------------------------
#define NCONV ((NBIG / 8 + NSMALL / 8 + 255) / 256)   // 1063

__global__ __launch_bounds__(256) void prep_kernel(
    const float* __restrict__ x, const float* __restrict__ c,
    const float* __restrict__ W0, const float* __restrict__ W1,
    const float* __restrict__ W2, const float* __restrict__ W3,
    const float* __restrict__ W4, const float* __restrict__ W5,
    const float* __restrict__ W6, const float* __restrict__ W7,
    __half* __restrict__ xh, __half* __restrict__ ch, __half* __restrict__ Wt)
{
    const int bid = blockIdx.x;
    const int tid = threadIdx.x;
    if (bid < NCONV) {
        const int i = bid * 256 + tid;
        const float* src;
        __half* dst;
        int k;
        if (i < NBIG / 8) { src = x; dst = xh; k = i; }
        else if (i < (NBIG + NSMALL) / 8) { src = c; dst = ch; k = i - NBIG / 8; }
        else return;
        const float4 f0 = reinterpret_cast<const float4*>(src)[k * 2];
        const float4 f1 = reinterpret_cast<const float4*>(src)[k * 2 + 1];
        __half2 hh[4];
        hh[0] = __floats2half2_rn(f0.x, f0.y);
        hh[1] = __floats2half2_rn(f0.z, f0.w);
        hh[2] = __floats2half2_rn(f1.x, f1.y);
        hh[3] = __floats2half2_rn(f1.z, f1.w);
        reinterpret_cast<uint4*>(dst)[k] = *reinterpret_cast<uint4*>(hh);
    } else {
        __shared__ __half t[32][33];
        const int r = bid - NCONV;
        const int z = r >> 8;
        const int by = (r >> 4) & 15;
        const int bx = r & 15;
        const float* src = (z == 0) ? W0 : (z == 1) ? W1 : (z == 2) ? W2 : (z == 3) ? W3
                         : (z == 4) ? W4 : (z == 5) ? W5 : (z == 6) ? W6 : W7;
        __half* dst = Wt + (size_t)z * WTSZ;
        const int tx = tid & 31, ty = tid >> 5;
        const int k0 = by * 32, n0 = bx * 32;
#pragma unroll
        for (int i = 0; i < 4; ++i)
            t[ty + i * 8][tx] = __float2half_rn(src[(size_t)(k0 + ty + i * 8) * 512 + n0 + tx]);
        __syncthreads();
#pragma unroll
        for (int i = 0; i < 4; ++i)
            dst[(size_t)(n0 + ty + i * 8) * 512 + k0 + tx] = t[tx][ty + i * 8];
    }
}

// ---------------------------------------------------------------------------
// fp16 GEMM core (128x128, register-double-buffered — measured best, frozen)
// ---------------------------------------------------------------------------
__device__ __forceinline__ void gemm_core(
    const __half* __restrict__ A, const __half* __restrict__ Wt,
    const float* __restrict__ bias,
    __half* __restrict__ outh, float* __restrict__ outf, float oscale,
    int Mrows, int m0, int n0)
{
    __shared__ __half sA[2][128][40];
    __shared__ __half sB[2][128][40];

    const int tid = threadIdx.x;
    const int lane = tid & 31;
    const int wid = tid >> 5;
    const int wm = (wid >> 1) * 32;
    const int wn = (wid & 1) * 64;
    const int g = lane >> 2;
    const int tg = lane & 3;

    const int ar = tid >> 1;
    const int ak = (tid & 1) * 16;
    const bool aok = (m0 + ar) < Mrows;
    const __half* aptr = A + (size_t)(m0 + ar) * 512 + ak;
    const __half* bptr = Wt + (size_t)(n0 + ar) * 512 + ak;

    const int arow = wm + (lane & 15);
    const int acol = (lane >> 4) * 8;
    const int brow = wn + ((lane >> 3) & 1) * 8 + (lane & 7);
    const int bcol = (lane >> 4) * 8;

    float acc[2][8][4];
#pragma unroll
    for (int im = 0; im < 2; ++im)
#pragma unroll
        for (int in = 0; in < 8; ++in)
#pragma unroll
            for (int j = 0; j < 4; ++j) acc[im][in][j] = 0.f;

    uint4 ra0, ra1, rb0, rb1;
    const uint4 z4 = make_uint4(0, 0, 0, 0);

    auto load_stage = [&](int k0) {
        ra0 = aok ? *reinterpret_cast<const uint4*>(aptr + k0) : z4;
        ra1 = aok ? *reinterpret_cast<const uint4*>(aptr + k0 + 8) : z4;
        rb0 = *reinterpret_cast<const uint4*>(bptr + k0);
        rb1 = *reinterpret_cast<const uint4*>(bptr + k0 + 8);
    };
    auto store_stage = [&](int buf) {
        *reinterpret_cast<uint4*>(&sA[buf][ar][ak]) = ra0;
        *reinterpret_cast<uint4*>(&sA[buf][ar][ak + 8]) = ra1;
        *reinterpret_cast<uint4*>(&sB[buf][ar][ak]) = rb0;
        *reinterpret_cast<uint4*>(&sB[buf][ar][ak + 8]) = rb1;
    };

    load_stage(0);
    store_stage(0);
    __syncthreads();

#pragma unroll 1
    for (int it = 0; it < 16; ++it) {
        const int buf = it & 1;
        if (it < 15) load_stage((it + 1) * 32);

#pragma unroll
        for (int kc = 0; kc < 32; kc += 16) {
            uint32_t a[2][4];
#pragma unroll
            for (int im = 0; im < 2; ++im)
                ldsm_x4(a[im][0], a[im][1], a[im][2], a[im][3],
                        smem_u32(&sA[buf][arow + im * 16][acol + kc]));
#pragma unroll
            for (int nq = 0; nq < 4; ++nq) {
                uint32_t b0, b1, b2, b3;
                ldsm_x4(b0, b1, b2, b3,
                        smem_u32(&sB[buf][brow + nq * 16][bcol + kc]));
#pragma unroll
                for (int im = 0; im < 2; ++im) {
                    mma16816(acc[im][2 * nq],     a[im][0], a[im][1], a[im][2], a[im][3], b0, b2);
                    mma16816(acc[im][2 * nq + 1], a[im][0], a[im][1], a[im][2], a[im][3], b1, b3);
                }
            }
        }
        if (it < 15) {
            store_stage(1 - buf);
            __syncthreads();
        }
    }

#pragma unroll
    for (int in = 0; in < 8; ++in) {
        const int col = n0 + wn + in * 8 + tg * 2;
        const float2 bb = *reinterpret_cast<const float2*>(bias + col);
#pragma unroll
        for (int im = 0; im < 2; ++im) {
            const int r0 = m0 + wm + im * 16 + g;
            const int r1 = r0 + 8;
            if (r0 < Mrows) {
                const float v0 = (acc[im][in][0] + bb.x) * oscale;
                const float v1 = (acc[im][in][1] + bb.y) * oscale;
                if (outh)
                    *reinterpret_cast<__half2*>(outh + (size_t)r0 * 512 + col) =
                        __floats2half2_rn(v0, v1);
                else
                    *reinterpret_cast<float2*>(outf + (size_t)r0 * 512 + col) =
                        make_float2(v0, v1);
            }
            if (r1 < Mrows) {
                const float v2 = (acc[im][in][2] + bb.x) * oscale;
                const float v3 = (acc[im][in][3] + bb.y) * oscale;
                if (outh)
                    *reinterpret_cast<__half2*>(outh + (size_t)r1 * 512 + col) =
                        __floats2half2_rn(v2, v3);
                else
                    *reinterpret_cast<float2*>(outf + (size_t)r1 * 512 + col) =
                        make_float2(v2, v3);
            }
        }
    }
}

// projections: Q(pre-scaled),K,V (3x128) + KC,VC (2x8) = 400 blocks
__global__ __launch_bounds__(256) void proj_kernel(
    const __half* __restrict__ xh, const __half* __restrict__ ch,
    const __half* __restrict__ Wt,
    const float* __restrict__ bq, const float* __restrict__ bk,
    const float* __restrict__ bv, const float* __restrict__ bkc,
    const float* __restrict__ bvc,
    __half* __restrict__ Qh, __half* __restrict__ Kh, __half* __restrict__ Vh,
    __half* __restrict__ KCh, __half* __restrict__ VCh)
{
    const int bid = blockIdx.x;
    const __half *A, *W;
    const float* bias;
    __half* out;
    float oscale = 1.0f;
    int Mrows, m0, n0;
    if (bid < 384) {
        const int t = bid / 128, l = bid % 128;
        m0 = (l >> 2) * 128;
        n0 = (l & 3) * 128;
        A = xh; Mrows = BT;
        W = Wt + (size_t)t * WTSZ;
        bias = (t == 0) ? bq : ((t == 1) ? bk : bv);
        out = (t == 0) ? Qh : ((t == 1) ? Kh : Vh);
        if (t == 0) oscale = QSCALE;
    } else {
        const int r = bid - 384;
        const int t = r / 8, l = r % 8;
        m0 = (l >> 2) * 128;
        n0 = (l & 3) * 128;
        A = ch; Mrows = MSMALL;
        W = Wt + (size_t)(3 + t) * WTSZ;
        bias = t ? bvc : bkc;
        out = t ? VCh : KCh;
    }
    gemm_core(A, W, bias, out, nullptr, oscale, Mrows, m0, n0);
}

__global__ __launch_bounds__(256) void gates_kernel(
    const __half* __restrict__ Yh, const __half* __restrict__ YCh,
    const __half* __restrict__ Wt,
    const float* __restrict__ bg1, const float* __restrict__ bg2,
    __half* __restrict__ G1, __half* __restrict__ G2)
{
    const int bid = blockIdx.x;
    const int t = bid >> 7;
    const int l = bid & 127;
    gemm_core(t ? YCh : Yh, Wt + (size_t)(5 + t) * WTSZ, t ? bg2 : bg1,
              t ? G2 : G1, nullptr, 1.0f, BT, (l >> 2) * 128, (l & 3) * 128);
}

__global__ __launch_bounds__(256) void final_gemm_kernel(
    const __half* __restrict__ F, const __half* __restrict__ Wt,
    const float* __restrict__ bp, float* __restrict__ out)
{
    const int l = blockIdx.x;
    gemm_core(F, Wt + 7ULL * WTSZ, bp, nullptr, out, 1.0f, BT,
              (l >> 2) * 128, (l & 3) * 128);
}

// ---------------------------------------------------------------------------
// Attention kernel, 4-way split-KV self-attention + cross. grid (80, B*H).
// Single __syncthreads per key tile. Partials stored in fp32 (R13 layout).
// ---------------------------------------------------------------------------
#define SAS 72
#define CPS 88

__global__ __launch_bounds__(256, 3) void attn_kernel(
    const __half* __restrict__ Q, const __half* __restrict__ K,
    const __half* __restrict__ V,
    const __half* __restrict__ Kc, const __half* __restrict__ Vc,
    const int* __restrict__ pad,
    float* __restrict__ po, float2* __restrict__ ml,
    __half* __restrict__ Yc)
{
    extern __shared__ __half smh[];

    const int bh = blockIdx.y;
    const int b = bh >> 3;
    const int h = bh & 7;
    const int tid = threadIdx.x;
    const int lane = tid & 31;
    const int wid = tid >> 5;
    const int g = lane >> 2;
    const int tg = lane & 3;
    const int wm = wid * 16;

    const size_t qbase = ((size_t)b * TLEN) * CDIM + h * 64;

    const int arow = wm + (lane & 15);
    const int acol = (lane >> 4) * 8;
    const int brow = ((lane >> 3) & 1) * 8 + (lane & 7);
    const int bcol = (lane >> 4) * 8;
    const int vrow = (lane & 7) + ((lane >> 4) & 1) * 8;
    const int vcol = ((lane >> 3) & 1) * 8;
    const int rA = wm + g;

    if (blockIdx.x < 64) {
        // ============ causal self-attention (split-KV quarter) ============
        __half* sQ = smh;                     // [128][72]
        __half* sP = sQ + 128 * SAS;          // [128][72]
        __half* sK = sP + 128 * SAS;          // [2][64][72]
        __half* sV = sK + 2 * 64 * SAS;       // [2][64][72]

        const int p = (int)blockIdx.x;
        const int qb = 15 - (p >> 2);
        const int quarter = p & 3;
        const int total = 2 * (qb + 1);
        const int jt0 = (total * quarter) >> 2;
        const int jtEnd = (total * (quarter + 1)) >> 2;
        const int nT = jtEnd - jt0;

        {
            const int r = tid >> 1, cb = (tid & 1) * 32;
            const uint4* src = reinterpret_cast<const uint4*>(
                Q + qbase + (size_t)(qb * 128 + r) * CDIM + cb);
            uint4* dst = reinterpret_cast<uint4*>(&sQ[r * SAS + cb]);
            dst[0] = src[0]; dst[1] = src[1]; dst[2] = src[2]; dst[3] = src[3];
        }

        const int kvr = tid >> 2, kvc = (tid & 3) * 16;

        auto prefetch = [&](int jt, int buf) {
            const size_t gofs = qbase + (size_t)(jt * 64 + kvr) * CDIM + kvc;
            const uint32_t kd = smem_u32(&sK[(buf * 64 + kvr) * SAS + kvc]);
            const uint32_t vd = smem_u32(&sV[(buf * 64 + kvr) * SAS + kvc]);
            cp16(kd, K + gofs);
            cp16(kd + 16, K + gofs + 8);
            cp16(vd, V + gofs);
            cp16(vd + 16, V + gofs + 8);
        };

        float o[8][4];
#pragma unroll
        for (int in = 0; in < 8; ++in)
#pragma unroll
            for (int j = 0; j < 4; ++j) o[in][j] = 0.f;
        float mrow[2] = {NEGB, NEGB};
        float lrow[2] = {0.f, 0.f};

        const int qrA = qb * 128 + rA;
        const int qrB = qrA + 8;

        if (nT > 0) {
            prefetch(jt0, 0);
            cp_commit();

#pragma unroll 1
            for (int t = 0; t < nT; ++t) {
                const int jt = jt0 + t;
                const int buf = t & 1;
                cp_wait<0>();
                __syncthreads();
                if (t + 1 < nT) {
                    prefetch(jt + 1, buf ^ 1);
                    cp_commit();
                }

                float s[8][4];
#pragma unroll
                for (int in = 0; in < 8; ++in)
#pragma unroll
                    for (int j = 0; j < 4; ++j) s[in][j] = 0.f;

#pragma unroll
                for (int kc = 0; kc < 64; kc += 16) {
                    uint32_t a0, a1, a2, a3;
                    ldsm_x4(a0, a1, a2, a3, smem_u32(&sQ[arow * SAS + acol + kc]));
#pragma unroll
                    for (int nq = 0; nq < 4; ++nq) {
                        uint32_t b0, b1, b2, b3;
                        ldsm_x4(b0, b1, b2, b3,
                                smem_u32(&sK[(buf * 64 + nq * 16 + brow) * SAS + bcol + kc]));
                        mma16816(s[2 * nq],     a0, a1, a2, a3, b0, b2);
                        mma16816(s[2 * nq + 1], a0, a1, a2, a3, b1, b3);
                    }
                }

                if (jt >= 2 * qb) {
#pragma unroll
                    for (int in = 0; in < 8; ++in) {
                        const int cj = jt * 64 + in * 8 + tg * 2;
                        if (cj     > qrA) s[in][0] = NEGB;
                        if (cj + 1 > qrA) s[in][1] = NEGB;
                        if (cj     > qrB) s[in][2] = NEGB;
                        if (cj + 1 > qrB) s[in][3] = NEGB;
                    }
                }

                float rmA = NEGB, rmB = NEGB;
#pragma unroll
                for (int in = 0; in < 8; ++in) {
                    rmA = fmaxf(rmA, fmaxf(s[in][0], s[in][1]));
                    rmB = fmaxf(rmB, fmaxf(s[in][2], s[in][3]));
                }
                rmA = fmaxf(rmA, __shfl_xor_sync(0xffffffffu, rmA, 1));
                rmA = fmaxf(rmA, __shfl_xor_sync(0xffffffffu, rmA, 2));
                rmB = fmaxf(rmB, __shfl_xor_sync(0xffffffffu, rmB, 1));
                rmB = fmaxf(rmB, __shfl_xor_sync(0xffffffffu, rmB, 2));

                const float mA = fmaxf(mrow[0], rmA);
                const float mB = fmaxf(mrow[1], rmB);
                const float cA = ex2(mrow[0] - mA);
                const float cB = ex2(mrow[1] - mB);

                float rsA = 0.f, rsB = 0.f;
#pragma unroll
                for (int in = 0; in < 8; ++in) {
                    const float p0 = ex2(s[in][0] - mA);
                    const float p1 = ex2(s[in][1] - mA);
                    const float p2 = ex2(s[in][2] - mB);
                    const float p3 = ex2(s[in][3] - mB);
                    rsA += p0 + p1;
                    rsB += p2 + p3;
                    const int col = in * 8 + tg * 2;
                    *reinterpret_cast<__half2*>(&sP[rA * SAS + col]) = __floats2half2_rn(p0, p1);
                    *reinterpret_cast<__half2*>(&sP[(rA + 8) * SAS + col]) = __floats2half2_rn(p2, p3);
                }
                rsA += __shfl_xor_sync(0xffffffffu, rsA, 1);
                rsA += __shfl_xor_sync(0xffffffffu, rsA, 2);
                rsB += __shfl_xor_sync(0xffffffffu, rsB, 1);
                rsB += __shfl_xor_sync(0xffffffffu, rsB, 2);

                lrow[0] = lrow[0] * cA + rsA;
                lrow[1] = lrow[1] * cB + rsB;
                mrow[0] = mA;
                mrow[1] = mB;

#pragma unroll
                for (int in = 0; in < 8; ++in) {
                    o[in][0] *= cA; o[in][1] *= cA;
                    o[in][2] *= cB; o[in][3] *= cB;
                }
                __syncwarp();

#pragma unroll
                for (int kc = 0; kc < 64; kc += 16) {
                    uint32_t a0, a1, a2, a3;
                    ldsm_x4(a0, a1, a2, a3, smem_u32(&sP[arow * SAS + acol + kc]));
#pragma unroll
                    for (int dq = 0; dq < 4; ++dq) {
                        uint32_t b0, b1, b2, b3;
                        ldsm_x4_t(b0, b1, b2, b3,
                                  smem_u32(&sV[(buf * 64 + kc + vrow) * SAS + dq * 16 + vcol]));
                        mma16816(o[2 * dq],     a0, a1, a2, a3, b0, b2);
                        mma16816(o[2 * dq + 1], a0, a1, a2, a3, b1, b3);
                    }
                }
            }
        }

        // write unnormalized partials (fp32) + per-row (m, l)
        const int rowgA = b * TLEN + qrA;
        const int rowgB = rowgA + 8;
        float* poA = po + (size_t)quarter * NBIG + (size_t)rowgA * 512 + h * 64;
        float* poB = po + (size_t)quarter * NBIG + (size_t)rowgB * 512 + h * 64;
#pragma unroll
        for (int in = 0; in < 8; ++in) {
            const int col = in * 8 + tg * 2;
            *reinterpret_cast<float2*>(poA + col) = make_float2(o[in][0], o[in][1]);
            *reinterpret_cast<float2*>(poB + col) = make_float2(o[in][2], o[in][3]);
        }
        if (tg == 0) {
            ml[(size_t)quarter * BT * HEADS + (size_t)rowgA * HEADS + h] =
                make_float2(mrow[0], lrow[0]);
            ml[(size_t)quarter * BT * HEADS + (size_t)rowgB * HEADS + h] =
                make_float2(mrow[1], lrow[1]);
        }
    } else {
        // =================== cross-attention (unchanged) ===================
        __half* sQ = smh;
        __half* sP = sQ + 128 * SAS;
        __half* sK = sP + 128 * CPS;
        __half* sV = sK + 80 * SAS;
        int* sF = (int*)(sV + 80 * SAS);

        const int qb = (int)blockIdx.x - 64;
        const size_t kbase = ((size_t)b * MLEN) * CDIM + h * 64;

        {
            const int r = tid >> 1, cb = (tid & 1) * 32;
            const uint4* src = reinterpret_cast<const uint4*>(
                Q + qbase + (size_t)(qb * 128 + r) * CDIM + cb);
            uint4* dst = reinterpret_cast<uint4*>(&sQ[r * SAS + cb]);
            dst[0] = src[0]; dst[1] = src[1]; dst[2] = src[2]; dst[3] = src[3];
        }
        {
            const int r = tid >> 1, cb = (tid & 1) * 32;
            if (r < 80) {
                uint4 kv0, kv1, kv2, kv3, vv0, vv1, vv2, vv3;
                if (r < MLEN) {
                    const uint4* ks = reinterpret_cast<const uint4*>(Kc + kbase + (size_t)r * CDIM + cb);
                    const uint4* vs = reinterpret_cast<const uint4*>(Vc + kbase + (size_t)r * CDIM + cb);
                    kv0 = ks[0]; kv1 = ks[1]; kv2 = ks[2]; kv3 = ks[3];
                    vv0 = vs[0]; vv1 = vs[1]; vv2 = vs[2]; vv3 = vs[3];
                } else {
                    kv0 = kv1 = kv2 = kv3 = make_uint4(0, 0, 0, 0);
                    vv0 = vv1 = vv2 = vv3 = kv0;
                }
                uint4* kd = reinterpret_cast<uint4*>(&sK[r * SAS + cb]);
                uint4* vd = reinterpret_cast<uint4*>(&sV[r * SAS + cb]);
                kd[0] = kv0; kd[1] = kv1; kd[2] = kv2; kd[3] = kv3;
                vd[0] = vv0; vd[1] = vv1; vd[2] = vv2; vd[3] = vv3;
            }
        }
        if (tid < 80) sF[tid] = (tid < MLEN) ? pad[b * MLEN + tid] : 0;
        __syncthreads();

        float s[10][4];
#pragma unroll
        for (int in = 0; in < 10; ++in)
#pragma unroll
            for (int j = 0; j < 4; ++j) s[in][j] = 0.f;

#pragma unroll
        for (int kc = 0; kc < 64; kc += 16) {
            uint32_t a0, a1, a2, a3;
            ldsm_x4(a0, a1, a2, a3, smem_u32(&sQ[arow * SAS + acol + kc]));
#pragma unroll
            for (int nq = 0; nq < 5; ++nq) {
                uint32_t b0, b1, b2, b3;
                ldsm_x4(b0, b1, b2, b3,
                        smem_u32(&sK[(nq * 16 + brow) * SAS + bcol + kc]));
                mma16816(s[2 * nq],     a0, a1, a2, a3, b0, b2);
                mma16816(s[2 * nq + 1], a0, a1, a2, a3, b1, b3);
            }
        }

#pragma unroll
        for (int in = 0; in < 10; ++in) {
            const int cj = in * 8 + tg * 2;
            if (sF[cj] == 0)     { s[in][0] = NEGB; s[in][2] = NEGB; }
            if (sF[cj + 1] == 0) { s[in][1] = NEGB; s[in][3] = NEGB; }
        }

        float rmA = NEGB, rmB = NEGB;
#pragma unroll
        for (int in = 0; in < 10; ++in) {
            rmA = fmaxf(rmA, fmaxf(s[in][0], s[in][1]));
            rmB = fmaxf(rmB, fmaxf(s[in][2], s[in][3]));
        }
        rmA = fmaxf(rmA, __shfl_xor_sync(0xffffffffu, rmA, 1));
        rmA = fmaxf(rmA, __shfl_xor_sync(0xffffffffu, rmA, 2));
        rmB = fmaxf(rmB, __shfl_xor_sync(0xffffffffu, rmB, 1));
        rmB = fmaxf(rmB, __shfl_xor_sync(0xffffffffu, rmB, 2));

        float rsA = 0.f, rsB = 0.f;
#pragma unroll
        for (int in = 0; in < 10; ++in) {
            const float p0 = ex2(s[in][0] - rmA);
            const float p1 = ex2(s[in][1] - rmA);
            const float p2 = ex2(s[in][2] - rmB);
            const float p3 = ex2(s[in][3] - rmB);
            rsA += p0 + p1;
            rsB += p2 + p3;
            const int col = in * 8 + tg * 2;
            *reinterpret_cast<__half2*>(&sP[rA * CPS + col]) = __floats2half2_rn(p0, p1);
            *reinterpret_cast<__half2*>(&sP[(rA + 8) * CPS + col]) = __floats2half2_rn(p2, p3);
        }
        rsA += __shfl_xor_sync(0xffffffffu, rsA, 1);
        rsA += __shfl_xor_sync(0xffffffffu, rsA, 2);
        rsB += __shfl_xor_sync(0xffffffffu, rsB, 1);
        rsB += __shfl_xor_sync(0xffffffffu, rsB, 2);
        __syncwarp();

        float o[8][4];
#pragma unroll
        for (int in = 0; in < 8; ++in)
#pragma unroll
            for (int j = 0; j < 4; ++j) o[in][j] = 0.f;

#pragma unroll
        for (int kc = 0; kc < 80; kc += 16) {
            uint32_t a0, a1, a2, a3;
            ldsm_x4(a0, a1, a2, a3, smem_u32(&sP[arow * CPS + acol + kc]));
#pragma unroll
            for (int dq = 0; dq < 4; ++dq) {
                uint32_t b0, b1, b2, b3;
                ldsm_x4_t(b0, b1, b2, b3,
                          smem_u32(&sV[(kc + vrow) * SAS + dq * 16 + vcol]));
                mma16816(o[2 * dq],     a0, a1, a2, a3, b0, b2);
                mma16816(o[2 * dq + 1], a0, a1, a2, a3, b1, b3);
            }
        }

        const float invA = (rsA > 0.f) ? (1.f / rsA) : 0.f;
        const float invB = (rsB > 0.f) ? (1.f / rsB) : 0.f;
        const int qrA = qb * 128 + rA;
        const int qrB = qrA + 8;
#pragma unroll
        for (int in = 0; in < 8; ++in) {
            const int col = in * 8 + tg * 2;
            *reinterpret_cast<__half2*>(Yc + qbase + (size_t)qrA * CDIM + col) =
                __floats2half2_rn(o[in][0] * invA, o[in][1] * invA);
            *reinterpret_cast<__half2*>(Yc + qbase + (size_t)qrB * CDIM + col) =
                __floats2half2_rn(o[in][2] * invB, o[in][3] * invB);
        }
    }
}

// ---------------------------------------------------------------------------
// merge 4 split-KV partials: Y = sum O_q*w_q / sum l_q*w_q, w_q = 2^(m_q - m)
// skips quarters with zero weight (empty splits). grid = BT*64/256 = 1024.
// ---------------------------------------------------------------------------
__global__ __launch_bounds__(256) void merge_kernel(
    const float* __restrict__ po, const float2* __restrict__ ml,
    __half* __restrict__ Y)
{
    const int idx = blockIdx.x * 256 + threadIdx.x;
    const int r = idx >> 6;
    const int c8 = (idx & 63) * 8;
    const int h = c8 >> 6;

    float2 mlq[NSPLIT];
#pragma unroll
    for (int q = 0; q < NSPLIT; ++q)
        mlq[q] = ml[(size_t)q * BT * HEADS + (size_t)r * HEADS + h];

    float m = mlq[0].x;
#pragma unroll
    for (int q = 1; q < NSPLIT; ++q) m = fmaxf(m, mlq[q].x);

    float w[NSPLIT], denom = 0.f;
#pragma unroll
    for (int q = 0; q < NSPLIT; ++q) {
        w[q] = ex2(mlq[q].x - m);
        denom += mlq[q].y * w[q];
    }
    const float inv = 1.f / denom;

    const size_t o = (size_t)r * 512 + c8;
    float acc[8];
#pragma unroll
    for (int j = 0; j < 8; ++j) acc[j] = 0.f;
#pragma unroll
    for (int q = 0; q < NSPLIT; ++q) {
        const float a = w[q] * inv;
        if (a != 0.f) {
            const float4 x0 = __ldg(reinterpret_cast<const float4*>(po + (size_t)q * NBIG + o));
            const float4 x1 = __ldg(reinterpret_cast<const float4*>(po + (size_t)q * NBIG + o + 4));
            acc[0] += x0.x * a; acc[1] += x0.y * a;
            acc[2] += x0.z * a; acc[3] += x0.w * a;
            acc[4] += x1.x * a; acc[5] += x1.y * a;
            acc[6] += x1.z * a; acc[7] += x1.w * a;
        }
    }

    __half2 outv[4];
    outv[0] = __floats2half2_rn(acc[0], acc[1]);
    outv[1] = __floats2half2_rn(acc[2], acc[3]);
    outv[2] = __floats2half2_rn(acc[4], acc[5]);
    outv[3] = __floats2half2_rn(acc[6], acc[7]);
    *reinterpret_cast<uint4*>(Y + o) = *reinterpret_cast<uint4*>(outv);
}

// ---------------------------------------------------------------------------
// fused = sigmoid(g1) * yc + sigmoid(g2) * y  (fp16 in/out)
// ---------------------------------------------------------------------------
__global__ __launch_bounds__(256) void gate_fuse_kernel(
    const __half* __restrict__ g1, const __half* __restrict__ g2,
    const __half* __restrict__ y, const __half* __restrict__ yc,
    __half* __restrict__ f)
{
    const int i = blockIdx.x * 256 + threadIdx.x;
    const uint4 ua = reinterpret_cast<const uint4*>(g1)[i];
    const uint4 ub = reinterpret_cast<const uint4*>(g2)[i];
    const uint4 uy = reinterpret_cast<const uint4*>(y)[i];
    const uint4 uc = reinterpret_cast<const uint4*>(yc)[i];
    const __half2* ha = reinterpret_cast<const __half2*>(&ua);
    const __half2* hb = reinterpret_cast<const __half2*>(&ub);
    const __half2* hy = reinterpret_cast<const __half2*>(&uy);
    const __half2* hc = reinterpret_cast<const __half2*>(&uc);
    __half2 ho[4];
#pragma unroll
    for (int k = 0; k < 4; ++k) {
        const float2 a = __half22float2(ha[k]);
        const float2 bg = __half22float2(hb[k]);
        const float2 yv = __half22float2(hy[k]);
        const float2 yw = __half22float2(hc[k]);
        ho[k] = __floats2half2_rn(sigf(a.x) * yw.x + sigf(bg.x) * yv.x,
                                  sigf(a.y) * yw.y + sigf(bg.y) * yv.y);
    }
    reinterpret_cast<uint4*>(f)[i] = *reinterpret_cast<uint4*>(ho);
}

// ---------------------------------------------------------------------------
// Launch
// ---------------------------------------------------------------------------
extern "C" void kernel_launch(void* const* d_in, const int* in_sizes, int n_in,
                              void* d_out, int out_size)
{
    const float* x  = (const float*)d_in[0];
    const float* c  = (const float*)d_in[1];
    const int* pad  = (const int*)d_in[3];
    const float* Wq = (const float*)d_in[4];
    const float* bq = (const float*)d_in[5];
    const float* Wk = (const float*)d_in[6];
    const float* bk = (const float*)d_in[7];
    const float* Wv = (const float*)d_in[8];
    const float* bv = (const float*)d_in[9];
    const float* Wkc = (const float*)d_in[10];
    const float* bkc = (const float*)d_in[11];
    const float* Wvc = (const float*)d_in[12];
    const float* bvc = (const float*)d_in[13];
    const float* Wg1 = (const float*)d_in[14];
    const float* bg1 = (const float*)d_in[15];
    const float* Wg2 = (const float*)d_in[16];
    const float* bg2 = (const float*)d_in[17];
    const float* Wp = (const float*)d_in[18];
    const float* bp = (const float*)d_in[19];
    float* out = (float*)d_out;

    __half* H = nullptr;
    cudaGetSymbolAddress((void**)&H, g_h);
    float* PO = nullptr;
    cudaGetSymbolAddress((void**)&PO, g_po);
    float2* ML = nullptr;
    cudaGetSymbolAddress((void**)&ML, g_ml);

    __half* XH  = H + 0ULL * NBIG;
    __half* Qh  = H + 1ULL * NBIG;
    __half* Kh  = H + 2ULL * NBIG;
    __half* Vh  = H + 3ULL * NBIG;
    __half* Yh  = H + 4ULL * NBIG;
    __half* YCh = H + 5ULL * NBIG;
    __half* G1h = H + 6ULL * NBIG;
    __half* G2h = H + 7ULL * NBIG;
    __half* Fh  = H + 8ULL * NBIG;
    __half* CH  = H + 9ULL * NBIG;
    __half* KCh = CH + NSMALL;
    __half* VCh = CH + 2ULL * NSMALL;
    __half* WT  = CH + 3ULL * NSMALL;

    const int SMEM_AT = (128 * SAS + 128 * SAS + 128 * SAS + 128 * SAS) * 2; // 73728
    cudaFuncSetAttribute(attn_kernel,
                         cudaFuncAttributeMaxDynamicSharedMemorySize, SMEM_AT);

    prep_kernel<<<NCONV + 2048, 256>>>(x, c, Wq, Wk, Wv, Wkc, Wvc, Wg1, Wg2, Wp,
                                       XH, CH, WT);

    proj_kernel<<<400, 256>>>(XH, CH, WT, bq, bk, bv, bkc, bvc,
                              Qh, Kh, Vh, KCh, VCh);

    attn_kernel<<<dim3(80, BATCH * HEADS), 256, SMEM_AT>>>(
        Qh, Kh, Vh, KCh, VCh, pad, PO, ML, YCh);
    merge_kernel<<<BT * 64 / 256, 256>>>(PO, ML, Yh);

    gates_kernel<<<256, 256>>>(Yh, YCh, WT, bg1, bg2, G1h, G2h);
    gate_fuse_kernel<<<NBIG / 8 / 256, 256>>>(G1h, G2h, Yh, YCh, Fh);
    final_gemm_kernel<<<128, 256>>>(Fh, WT, bp, out);
}

// round 16
// speedup vs baseline: 1.6021x; 1.0812x over previous
#include <cuda_runtime.h>
#include <cuda_fp16.h>
#include <math.h>
#include <stdint.h>

#define BATCH 2
#define TLEN 2048
#define MLEN 77
#define CDIM 512
#define HEADS 8
#define BT 4096
#define NBIG 2097152
#define NSMALL 78848
#define MSMALL 154
#define WTSZ 262144
#define QSCALE 0.18033688011112042f   // 0.125 * log2(e)
#define NEGB (-30000.0f)
#define NSPLIT 4

// fp16 scratch: XH,Q,K,V,Y,YC,G1,G2,F (9*NBIG), CH,KC,VC (3*NSMALL), WT[8]
__device__ __half g_h[9ULL * NBIG + 3ULL * NSMALL + 8ULL * WTSZ];
// split-KV partials: unnormalized O (fp32) for NSPLIT quarters + per-row (m,l)
__device__ float g_po[(size_t)NSPLIT * NBIG];
__device__ float2 g_ml[(size_t)NSPLIT * BT * HEADS];

// ---------------------------------------------------------------------------
// helpers
// ---------------------------------------------------------------------------
__device__ __forceinline__ uint32_t smem_u32(const void* p) {
    return (uint32_t)__cvta_generic_to_shared(p);
}
__device__ __forceinline__ void ldsm_x4(uint32_t& r0, uint32_t& r1,
                                        uint32_t& r2, uint32_t& r3, uint32_t a) {
    asm volatile("ldmatrix.sync.aligned.m8n8.x4.shared.b16 {%0,%1,%2,%3}, [%4];"
                 : "=r"(r0), "=r"(r1), "=r"(r2), "=r"(r3) : "r"(a));
}
__device__ __forceinline__ void ldsm_x4_t(uint32_t& r0, uint32_t& r1,
                                          uint32_t& r2, uint32_t& r3, uint32_t a) {
    asm volatile("ldmatrix.sync.aligned.m8n8.x4.trans.shared.b16 {%0,%1,%2,%3}, [%4];"
                 : "=r"(r0), "=r"(r1), "=r"(r2), "=r"(r3) : "r"(a));
}
__device__ __forceinline__ void mma16816(float (&d)[4],
    uint32_t a0, uint32_t a1, uint32_t a2, uint32_t a3, uint32_t b0, uint32_t b1) {
    asm volatile(
        "mma.sync.aligned.m16n8k16.row.col.f32.f16.f16.f32 "
        "{%0,%1,%2,%3}, {%4,%5,%6,%7}, {%8,%9}, {%0,%1,%2,%3};\n"
        : "+f"(d[0]), "+f"(d[1]), "+f"(d[2]), "+f"(d[3])
        : "r"(a0), "r"(a1), "r"(a2), "r"(a3), "r"(b0), "r"(b1));
}
__device__ __forceinline__ float ex2(float x) {
    float r;
    asm("ex2.approx.ftz.f32 %0, %1;" : "=f"(r) : "f"(x));
    return r;
}
__device__ __forceinline__ float sigf(float x) {
    return 1.f / (1.f + __expf(-x));
}
__device__ __forceinline__ void cp16(uint32_t s, const void* g) {
    asm volatile("cp.async.cg.shared.global [%0], [%1], 16;" :: "r"(s), "l"(g));
}
__device__ __forceinline__ void cp16z(uint32_t s, const void* g, int srcsz) {
    asm volatile("cp.async.cg.shared.global [%0], [%1], 16, %2;"
                 :: "r"(s), "l"(g), "r"(srcsz));
}
__device__ __forceinline__ void cp_commit() {
    asm volatile("cp.async.commit_group;");
}
template <int N>
__device__ __forceinline__ void cp_wait() {
    asm volatile("cp.async.wait_group %0;" :: "n"(N));
}

// ---------------------------------------------------------------------------
// merged prep: blocks [0, NCONV) convert x,c -> fp16;
//              blocks [NCONV, NCONV+2048) transpose 8 weights -> fp16 [n][k]
// ---------------------------------------------------------------------------
#define NCONV ((NBIG / 8 + NSMALL / 8 + 255) / 256)   // 1063

__global__ __launch_bounds__(256) void prep_kernel(
    const float* __restrict__ x, const float* __restrict__ c,
    const float* __restrict__ W0, const float* __restrict__ W1,
    const float* __restrict__ W2, const float* __restrict__ W3,
    const float* __restrict__ W4, const float* __restrict__ W5,
    const float* __restrict__ W6, const float* __restrict__ W7,
    __half* __restrict__ xh, __half* __restrict__ ch, __half* __restrict__ Wt)
{
    const int bid = blockIdx.x;
    const int tid = threadIdx.x;
    if (bid < NCONV) {
        const int i = bid * 256 + tid;
        const float* src;
        __half* dst;
        int k;
        if (i < NBIG / 8) { src = x; dst = xh; k = i; }
        else if (i < (NBIG + NSMALL) / 8) { src = c; dst = ch; k = i - NBIG / 8; }
        else return;
        const float4 f0 = reinterpret_cast<const float4*>(src)[k * 2];
        const float4 f1 = reinterpret_cast<const float4*>(src)[k * 2 + 1];
        __half2 hh[4];
        hh[0] = __floats2half2_rn(f0.x, f0.y);
        hh[1] = __floats2half2_rn(f0.z, f0.w);
        hh[2] = __floats2half2_rn(f1.x, f1.y);
        hh[3] = __floats2half2_rn(f1.z, f1.w);
        reinterpret_cast<uint4*>(dst)[k] = *reinterpret_cast<uint4*>(hh);
    } else {
        __shared__ __half t[32][33];
        const int r = bid - NCONV;
        const int z = r >> 8;
        const int by = (r >> 4) & 15;
        const int bx = r & 15;
        const float* src = (z == 0) ? W0 : (z == 1) ? W1 : (z == 2) ? W2 : (z == 3) ? W3
                         : (z == 4) ? W4 : (z == 5) ? W5 : (z == 6) ? W6 : W7;
        __half* dst = Wt + (size_t)z * WTSZ;
        const int tx = tid & 31, ty = tid >> 5;
        const int k0 = by * 32, n0 = bx * 32;
#pragma unroll
        for (int i = 0; i < 4; ++i)
            t[ty + i * 8][tx] = __float2half_rn(src[(size_t)(k0 + ty + i * 8) * 512 + n0 + tx]);
        __syncthreads();
#pragma unroll
        for (int i = 0; i < 4; ++i)
            dst[(size_t)(n0 + ty + i * 8) * 512 + k0 + tx] = t[tx][ty + i * 8];
    }
}

// ---------------------------------------------------------------------------
// fp16 GEMM core, 128x128 tile, cp.async 2-stage, SINGLE sync per k-iter
// (same pipeline structure as the proven attn kernel).
// ---------------------------------------------------------------------------
__device__ __forceinline__ void gemm_core(
    const __half* __restrict__ A, const __half* __restrict__ Wt,
    const float* __restrict__ bias,
    __half* __restrict__ outh, float* __restrict__ outf, float oscale,
    int Mrows, int m0, int n0)
{
    __shared__ __half sA[2][128][40];
    __shared__ __half sB[2][128][40];

    const int tid = threadIdx.x;
    const int lane = tid & 31;
    const int wid = tid >> 5;
    const int wm = (wid >> 1) * 32;
    const int wn = (wid & 1) * 64;
    const int g = lane >> 2;
    const int tg = lane & 3;

    const int ar = tid >> 1;
    const int ak = (tid & 1) * 16;
    const int asz = ((m0 + ar) < Mrows) ? 16 : 0;
    const __half* aptr = A + (size_t)(m0 + ar) * 512 + ak;
    const __half* bptr = Wt + (size_t)(n0 + ar) * 512 + ak;

    const int arow = wm + (lane & 15);
    const int acol = (lane >> 4) * 8;
    const int brow = wn + ((lane >> 3) & 1) * 8 + (lane & 7);
    const int bcol = (lane >> 4) * 8;

    float acc[2][8][4];
#pragma unroll
    for (int im = 0; im < 2; ++im)
#pragma unroll
        for (int in = 0; in < 8; ++in)
#pragma unroll
            for (int j = 0; j < 4; ++j) acc[im][in][j] = 0.f;

    auto stage = [&](int it) {
        const int buf = it & 1;
        const int k0 = it * 32;
        cp16z(smem_u32(&sA[buf][ar][ak]), aptr + k0, asz);
        cp16z(smem_u32(&sA[buf][ar][ak + 8]), aptr + k0 + 8, asz);
        cp16(smem_u32(&sB[buf][ar][ak]), bptr + k0);
        cp16(smem_u32(&sB[buf][ar][ak + 8]), bptr + k0 + 8);
        cp_commit();
    };

    stage(0);

#pragma unroll 1
    for (int it = 0; it < 16; ++it) {
        const int buf = it & 1;
        cp_wait<0>();
        __syncthreads();
        if (it < 15) stage(it + 1);

#pragma unroll
        for (int kc = 0; kc < 32; kc += 16) {
            uint32_t a[2][4];
#pragma unroll
            for (int im = 0; im < 2; ++im)
                ldsm_x4(a[im][0], a[im][1], a[im][2], a[im][3],
                        smem_u32(&sA[buf][arow + im * 16][acol + kc]));
#pragma unroll
            for (int nq = 0; nq < 4; ++nq) {
                uint32_t b0, b1, b2, b3;
                ldsm_x4(b0, b1, b2, b3,
                        smem_u32(&sB[buf][brow + nq * 16][bcol + kc]));
#pragma unroll
                for (int im = 0; im < 2; ++im) {
                    mma16816(acc[im][2 * nq],     a[im][0], a[im][1], a[im][2], a[im][3], b0, b2);
                    mma16816(acc[im][2 * nq + 1], a[im][0], a[im][1], a[im][2], a[im][3], b1, b3);
                }
            }
        }
    }

#pragma unroll
    for (int in = 0; in < 8; ++in) {
        const int col = n0 + wn + in * 8 + tg * 2;
        const float2 bb = *reinterpret_cast<const float2*>(bias + col);
#pragma unroll
        for (int im = 0; im < 2; ++im) {
            const int r0 = m0 + wm + im * 16 + g;
            const int r1 = r0 + 8;
            if (r0 < Mrows) {
                const float v0 = (acc[im][in][0] + bb.x) * oscale;
                const float v1 = (acc[im][in][1] + bb.y) * oscale;
                if (outh)
                    *reinterpret_cast<__half2*>(outh + (size_t)r0 * 512 + col) =
                        __floats2half2_rn(v0, v1);
                else
                    *reinterpret_cast<float2*>(outf + (size_t)r0 * 512 + col) =
                        make_float2(v0, v1);
            }
            if (r1 < Mrows) {
                const float v2 = (acc[im][in][2] + bb.x) * oscale;
                const float v3 = (acc[im][in][3] + bb.y) * oscale;
                if (outh)
                    *reinterpret_cast<__half2*>(outh + (size_t)r1 * 512 + col) =
                        __floats2half2_rn(v2, v3);
                else
                    *reinterpret_cast<float2*>(outf + (size_t)r1 * 512 + col) =
                        make_float2(v2, v3);
            }
        }
    }
}

// projections: Q(pre-scaled),K,V (3x128) + KC,VC (2x8) = 400 blocks
__global__ __launch_bounds__(256) void proj_kernel(
    const __half* __restrict__ xh, const __half* __restrict__ ch,
    const __half* __restrict__ Wt,
    const float* __restrict__ bq, const float* __restrict__ bk,
    const float* __restrict__ bv, const float* __restrict__ bkc,
    const float* __restrict__ bvc,
    __half* __restrict__ Qh, __half* __restrict__ Kh, __half* __restrict__ Vh,
    __half* __restrict__ KCh, __half* __restrict__ VCh)
{
    const int bid = blockIdx.x;
    const __half *A, *W;
    const float* bias;
    __half* out;
    float oscale = 1.0f;
    int Mrows, m0, n0;
    if (bid < 384) {
        const int t = bid / 128, l = bid % 128;
        m0 = (l >> 2) * 128;
        n0 = (l & 3) * 128;
        A = xh; Mrows = BT;
        W = Wt + (size_t)t * WTSZ;
        bias = (t == 0) ? bq : ((t == 1) ? bk : bv);
        out = (t == 0) ? Qh : ((t == 1) ? Kh : Vh);
        if (t == 0) oscale = QSCALE;
    } else {
        const int r = bid - 384;
        const int t = r / 8, l = r % 8;
        m0 = (l >> 2) * 128;
        n0 = (l & 3) * 128;
        A = ch; Mrows = MSMALL;
        W = Wt + (size_t)(3 + t) * WTSZ;
        bias = t ? bvc : bkc;
        out = t ? VCh : KCh;
    }
    gemm_core(A, W, bias, out, nullptr, oscale, Mrows, m0, n0);
}

__global__ __launch_bounds__(256) void gates_kernel(
    const __half* __restrict__ Yh, const __half* __restrict__ YCh,
    const __half* __restrict__ Wt,
    const float* __restrict__ bg1, const float* __restrict__ bg2,
    __half* __restrict__ G1, __half* __restrict__ G2)
{
    const int bid = blockIdx.x;
    const int t = bid >> 7;
    const int l = bid & 127;
    gemm_core(t ? YCh : Yh, Wt + (size_t)(5 + t) * WTSZ, t ? bg2 : bg1,
              t ? G2 : G1, nullptr, 1.0f, BT, (l >> 2) * 128, (l & 3) * 128);
}

__global__ __launch_bounds__(256) void final_gemm_kernel(
    const __half* __restrict__ F, const __half* __restrict__ Wt,
    const float* __restrict__ bp, float* __restrict__ out)
{
    const int l = blockIdx.x;
    gemm_core(F, Wt + 7ULL * WTSZ, bp, nullptr, out, 1.0f, BT,
              (l >> 2) * 128, (l & 3) * 128);
}

// ---------------------------------------------------------------------------
// Attention kernel, 4-way split-KV self-attention + cross. grid (80, B*H).
// Single __syncthreads per key tile. Partials fp32 (R13/R15 layout, frozen).
// ---------------------------------------------------------------------------
#define SAS 72
#define CPS 88

__global__ __launch_bounds__(256, 3) void attn_kernel(
    const __half* __restrict__ Q, const __half* __restrict__ K,
    const __half* __restrict__ V,
    const __half* __restrict__ Kc, const __half* __restrict__ Vc,
    const int* __restrict__ pad,
    float* __restrict__ po, float2* __restrict__ ml,
    __half* __restrict__ Yc)
{
    extern __shared__ __half smh[];

    const int bh = blockIdx.y;
    const int b = bh >> 3;
    const int h = bh & 7;
    const int tid = threadIdx.x;
    const int lane = tid & 31;
    const int wid = tid >> 5;
    const int g = lane >> 2;
    const int tg = lane & 3;
    const int wm = wid * 16;

    const size_t qbase = ((size_t)b * TLEN) * CDIM + h * 64;

    const int arow = wm + (lane & 15);
    const int acol = (lane >> 4) * 8;
    const int brow = ((lane >> 3) & 1) * 8 + (lane & 7);
    const int bcol = (lane >> 4) * 8;
    const int vrow = (lane & 7) + ((lane >> 4) & 1) * 8;
    const int vcol = ((lane >> 3) & 1) * 8;
    const int rA = wm + g;

    if (blockIdx.x < 64) {
        __half* sQ = smh;                     // [128][72]
        __half* sP = sQ + 128 * SAS;          // [128][72]
        __half* sK = sP + 128 * SAS;          // [2][64][72]
        __half* sV = sK + 2 * 64 * SAS;       // [2][64][72]

        const int p = (int)blockIdx.x;
        const int qb = 15 - (p >> 2);
        const int quarter = p & 3;
        const int total = 2 * (qb + 1);
        const int jt0 = (total * quarter) >> 2;
        const int jtEnd = (total * (quarter + 1)) >> 2;
        const int nT = jtEnd - jt0;

        {
            const int r = tid >> 1, cb = (tid & 1) * 32;
            const uint4* src = reinterpret_cast<const uint4*>(
                Q + qbase + (size_t)(qb * 128 + r) * CDIM + cb);
            uint4* dst = reinterpret_cast<uint4*>(&sQ[r * SAS + cb]);
            dst[0] = src[0]; dst[1] = src[1]; dst[2] = src[2]; dst[3] = src[3];
        }

        const int kvr = tid >> 2, kvc = (tid & 3) * 16;

        auto prefetch = [&](int jt, int buf) {
            const size_t gofs = qbase + (size_t)(jt * 64 + kvr) * CDIM + kvc;
            const uint32_t kd = smem_u32(&sK[(buf * 64 + kvr) * SAS + kvc]);
            const uint32_t vd = smem_u32(&sV[(buf * 64 + kvr) * SAS + kvc]);
            cp16(kd, K + gofs);
            cp16(kd + 16, K + gofs + 8);
            cp16(vd, V + gofs);
            cp16(vd + 16, V + gofs + 8);
        };

        float o[8][4];
#pragma unroll
        for (int in = 0; in < 8; ++in)
#pragma unroll
            for (int j = 0; j < 4; ++j) o[in][j] = 0.f;
        float mrow[2] = {NEGB, NEGB};
        float lrow[2] = {0.f, 0.f};

        const int qrA = qb * 128 + rA;
        const int qrB = qrA + 8;

        if (nT > 0) {
            prefetch(jt0, 0);
            cp_commit();

#pragma unroll 1
            for (int t = 0; t < nT; ++t) {
                const int jt = jt0 + t;
                const int buf = t & 1;
                cp_wait<0>();
                __syncthreads();
                if (t + 1 < nT) {
                    prefetch(jt + 1, buf ^ 1);
                    cp_commit();
                }

                float s[8][4];
#pragma unroll
                for (int in = 0; in < 8; ++in)
#pragma unroll
                    for (int j = 0; j < 4; ++j) s[in][j] = 0.f;

#pragma unroll
                for (int kc = 0; kc < 64; kc += 16) {
                    uint32_t a0, a1, a2, a3;
                    ldsm_x4(a0, a1, a2, a3, smem_u32(&sQ[arow * SAS + acol + kc]));
#pragma unroll
                    for (int nq = 0; nq < 4; ++nq) {
                        uint32_t b0, b1, b2, b3;
                        ldsm_x4(b0, b1, b2, b3,
                                smem_u32(&sK[(buf * 64 + nq * 16 + brow) * SAS + bcol + kc]));
                        mma16816(s[2 * nq],     a0, a1, a2, a3, b0, b2);
                        mma16816(s[2 * nq + 1], a0, a1, a2, a3, b1, b3);
                    }
                }

                if (jt >= 2 * qb) {
#pragma unroll
                    for (int in = 0; in < 8; ++in) {
                        const int cj = jt * 64 + in * 8 + tg * 2;
                        if (cj     > qrA) s[in][0] = NEGB;
                        if (cj + 1 > qrA) s[in][1] = NEGB;
                        if (cj     > qrB) s[in][2] = NEGB;
                        if (cj + 1 > qrB) s[in][3] = NEGB;
                    }
                }

                float rmA = NEGB, rmB = NEGB;
#pragma unroll
                for (int in = 0; in < 8; ++in) {
                    rmA = fmaxf(rmA, fmaxf(s[in][0], s[in][1]));
                    rmB = fmaxf(rmB, fmaxf(s[in][2], s[in][3]));
                }
                rmA = fmaxf(rmA, __shfl_xor_sync(0xffffffffu, rmA, 1));
                rmA = fmaxf(rmA, __shfl_xor_sync(0xffffffffu, rmA, 2));
                rmB = fmaxf(rmB, __shfl_xor_sync(0xffffffffu, rmB, 1));
                rmB = fmaxf(rmB, __shfl_xor_sync(0xffffffffu, rmB, 2));

                const float mA = fmaxf(mrow[0], rmA);
                const float mB = fmaxf(mrow[1], rmB);
                const float cA = ex2(mrow[0] - mA);
                const float cB = ex2(mrow[1] - mB);

                float rsA = 0.f, rsB = 0.f;
#pragma unroll
                for (int in = 0; in < 8; ++in) {
                    const float p0 = ex2(s[in][0] - mA);
                    const float p1 = ex2(s[in][1] - mA);
                    const float p2 = ex2(s[in][2] - mB);
                    const float p3 = ex2(s[in][3] - mB);
                    rsA += p0 + p1;
                    rsB += p2 + p3;
                    const int col = in * 8 + tg * 2;
                    *reinterpret_cast<__half2*>(&sP[rA * SAS + col]) = __floats2half2_rn(p0, p1);
                    *reinterpret_cast<__half2*>(&sP[(rA + 8) * SAS + col]) = __floats2half2_rn(p2, p3);
                }
                rsA += __shfl_xor_sync(0xffffffffu, rsA, 1);
                rsA += __shfl_xor_sync(0xffffffffu, rsA, 2);
                rsB += __shfl_xor_sync(0xffffffffu, rsB, 1);
                rsB += __shfl_xor_sync(0xffffffffu, rsB, 2);

                lrow[0] = lrow[0] * cA + rsA;
                lrow[1] = lrow[1] * cB + rsB;
                mrow[0] = mA;
                mrow[1] = mB;

#pragma unroll
                for (int in = 0; in < 8; ++in) {
                    o[in][0] *= cA; o[in][1] *= cA;
                    o[in][2] *= cB; o[in][3] *= cB;
                }
                __syncwarp();

#pragma unroll
                for (int kc = 0; kc < 64; kc += 16) {
                    uint32_t a0, a1, a2, a3;
                    ldsm_x4(a0, a1, a2, a3, smem_u32(&sP[arow * SAS + acol + kc]));
#pragma unroll
                    for (int dq = 0; dq < 4; ++dq) {
                        uint32_t b0, b1, b2, b3;
                        ldsm_x4_t(b0, b1, b2, b3,
                                  smem_u32(&sV[(buf * 64 + kc + vrow) * SAS + dq * 16 + vcol]));
                        mma16816(o[2 * dq],     a0, a1, a2, a3, b0, b2);
                        mma16816(o[2 * dq + 1], a0, a1, a2, a3, b1, b3);
                    }
                }
            }
        }

        const int rowgA = b * TLEN + qrA;
        const int rowgB = rowgA + 8;
        float* poA = po + (size_t)quarter * NBIG + (size_t)rowgA * 512 + h * 64;
        float* poB = po + (size_t)quarter * NBIG + (size_t)rowgB * 512 + h * 64;
#pragma unroll
        for (int in = 0; in < 8; ++in) {
            const int col = in * 8 + tg * 2;
            *reinterpret_cast<float2*>(poA + col) = make_float2(o[in][0], o[in][1]);
            *reinterpret_cast<float2*>(poB + col) = make_float2(o[in][2], o[in][3]);
        }
        if (tg == 0) {
            ml[(size_t)quarter * BT * HEADS + (size_t)rowgA * HEADS + h] =
                make_float2(mrow[0], lrow[0]);
            ml[(size_t)quarter * BT * HEADS + (size_t)rowgB * HEADS + h] =
                make_float2(mrow[1], lrow[1]);
        }
    } else {
        // =================== cross-attention (unchanged) ===================
        __half* sQ = smh;
        __half* sP = sQ + 128 * SAS;
        __half* sK = sP + 128 * CPS;
        __half* sV = sK + 80 * SAS;
        int* sF = (int*)(sV + 80 * SAS);

        const int qb = (int)blockIdx.x - 64;
        const size_t kbase = ((size_t)b * MLEN) * CDIM + h * 64;

        {
            const int r = tid >> 1, cb = (tid & 1) * 32;
            const uint4* src = reinterpret_cast<const uint4*>(
                Q + qbase + (size_t)(qb * 128 + r) * CDIM + cb);
            uint4* dst = reinterpret_cast<uint4*>(&sQ[r * SAS + cb]);
            dst[0] = src[0]; dst[1] = src[1]; dst[2] = src[2]; dst[3] = src[3];
        }
        {
            const int r = tid >> 1, cb = (tid & 1) * 32;
            if (r < 80) {
                uint4 kv0, kv1, kv2, kv3, vv0, vv1, vv2, vv3;
                if (r < MLEN) {
                    const uint4* ks = reinterpret_cast<const uint4*>(Kc + kbase + (size_t)r * CDIM + cb);
                    const uint4* vs = reinterpret_cast<const uint4*>(Vc + kbase + (size_t)r * CDIM + cb);
                    kv0 = ks[0]; kv1 = ks[1]; kv2 = ks[2]; kv3 = ks[3];
                    vv0 = vs[0]; vv1 = vs[1]; vv2 = vs[2]; vv3 = vs[3];
                } else {
                    kv0 = kv1 = kv2 = kv3 = make_uint4(0, 0, 0, 0);
                    vv0 = vv1 = vv2 = vv3 = kv0;
                }
                uint4* kd = reinterpret_cast<uint4*>(&sK[r * SAS + cb]);
                uint4* vd = reinterpret_cast<uint4*>(&sV[r * SAS + cb]);
                kd[0] = kv0; kd[1] = kv1; kd[2] = kv2; kd[3] = kv3;
                vd[0] = vv0; vd[1] = vv1; vd[2] = vv2; vd[3] = vv3;
            }
        }
        if (tid < 80) sF[tid] = (tid < MLEN) ? pad[b * MLEN + tid] : 0;
        __syncthreads();

        float s[10][4];
#pragma unroll
        for (int in = 0; in < 10; ++in)
#pragma unroll
            for (int j = 0; j < 4; ++j) s[in][j] = 0.f;

#pragma unroll
        for (int kc = 0; kc < 64; kc += 16) {
            uint32_t a0, a1, a2, a3;
            ldsm_x4(a0, a1, a2, a3, smem_u32(&sQ[arow * SAS + acol + kc]));
#pragma unroll
            for (int nq = 0; nq < 5; ++nq) {
                uint32_t b0, b1, b2, b3;
                ldsm_x4(b0, b1, b2, b3,
                        smem_u32(&sK[(nq * 16 + brow) * SAS + bcol + kc]));
                mma16816(s[2 * nq],     a0, a1, a2, a3, b0, b2);
                mma16816(s[2 * nq + 1], a0, a1, a2, a3, b1, b3);
            }
        }

#pragma unroll
        for (int in = 0; in < 10; ++in) {
            const int cj = in * 8 + tg * 2;
            if (sF[cj] == 0)     { s[in][0] = NEGB; s[in][2] = NEGB; }
            if (sF[cj + 1] == 0) { s[in][1] = NEGB; s[in][3] = NEGB; }
        }

        float rmA = NEGB, rmB = NEGB;
#pragma unroll
        for (int in = 0; in < 10; ++in) {
            rmA = fmaxf(rmA, fmaxf(s[in][0], s[in][1]));
            rmB = fmaxf(rmB, fmaxf(s[in][2], s[in][3]));
        }
        rmA = fmaxf(rmA, __shfl_xor_sync(0xffffffffu, rmA, 1));
        rmA = fmaxf(rmA, __shfl_xor_sync(0xffffffffu, rmA, 2));
        rmB = fmaxf(rmB, __shfl_xor_sync(0xffffffffu, rmB, 1));
        rmB = fmaxf(rmB, __shfl_xor_sync(0xffffffffu, rmB, 2));

        float rsA = 0.f, rsB = 0.f;
#pragma unroll
        for (int in = 0; in < 10; ++in) {
            const float p0 = ex2(s[in][0] - rmA);
            const float p1 = ex2(s[in][1] - rmA);
            const float p2 = ex2(s[in][2] - rmB);
            const float p3 = ex2(s[in][3] - rmB);
            rsA += p0 + p1;
            rsB += p2 + p3;
            const int col = in * 8 + tg * 2;
            *reinterpret_cast<__half2*>(&sP[rA * CPS + col]) = __floats2half2_rn(p0, p1);
            *reinterpret_cast<__half2*>(&sP[(rA + 8) * CPS + col]) = __floats2half2_rn(p2, p3);
        }
        rsA += __shfl_xor_sync(0xffffffffu, rsA, 1);
        rsA += __shfl_xor_sync(0xffffffffu, rsA, 2);
        rsB += __shfl_xor_sync(0xffffffffu, rsB, 1);
        rsB += __shfl_xor_sync(0xffffffffu, rsB, 2);
        __syncwarp();

        float o[8][4];
#pragma unroll
        for (int in = 0; in < 8; ++in)
#pragma unroll
            for (int j = 0; j < 4; ++j) o[in][j] = 0.f;

#pragma unroll
        for (int kc = 0; kc < 80; kc += 16) {
            uint32_t a0, a1, a2, a3;
            ldsm_x4(a0, a1, a2, a3, smem_u32(&sP[arow * CPS + acol + kc]));
#pragma unroll
            for (int dq = 0; dq < 4; ++dq) {
                uint32_t b0, b1, b2, b3;
                ldsm_x4_t(b0, b1, b2, b3,
                          smem_u32(&sV[(kc + vrow) * SAS + dq * 16 + vcol]));
                mma16816(o[2 * dq],     a0, a1, a2, a3, b0, b2);
                mma16816(o[2 * dq + 1], a0, a1, a2, a3, b1, b3);
            }
        }

        const float invA = (rsA > 0.f) ? (1.f / rsA) : 0.f;
        const float invB = (rsB > 0.f) ? (1.f / rsB) : 0.f;
        const int qrA = qb * 128 + rA;
        const int qrB = qrA + 8;
#pragma unroll
        for (int in = 0; in < 8; ++in) {
            const int col = in * 8 + tg * 2;
            *reinterpret_cast<__half2*>(Yc + qbase + (size_t)qrA * CDIM + col) =
                __floats2half2_rn(o[in][0] * invA, o[in][1] * invA);
            *reinterpret_cast<__half2*>(Yc + qbase + (size_t)qrB * CDIM + col) =
                __floats2half2_rn(o[in][2] * invB, o[in][3] * invB);
        }
    }
}

// ---------------------------------------------------------------------------
// merge 4 split-KV partials: Y = sum O_q*w_q / sum l_q*w_q, w_q = 2^(m_q - m)
// ---------------------------------------------------------------------------
__global__ __launch_bounds__(256) void merge_kernel(
    const float* __restrict__ po, const float2* __restrict__ ml,
    __half* __restrict__ Y)
{
    const int idx = blockIdx.x * 256 + threadIdx.x;
    const int r = idx >> 6;
    const int c8 = (idx & 63) * 8;
    const int h = c8 >> 6;

    float2 mlq[NSPLIT];
#pragma unroll
    for (int q = 0; q < NSPLIT; ++q)
        mlq[q] = ml[(size_t)q * BT * HEADS + (size_t)r * HEADS + h];

    float m = mlq[0].x;
#pragma unroll
    for (int q = 1; q < NSPLIT; ++q) m = fmaxf(m, mlq[q].x);

    float w[NSPLIT], denom = 0.f;
#pragma unroll
    for (int q = 0; q < NSPLIT; ++q) {
        w[q] = ex2(mlq[q].x - m);
        denom += mlq[q].y * w[q];
    }
    const float inv = 1.f / denom;

    const size_t o = (size_t)r * 512 + c8;
    float acc[8];
#pragma unroll
    for (int j = 0; j < 8; ++j) acc[j] = 0.f;
#pragma unroll
    for (int q = 0; q < NSPLIT; ++q) {
        const float a = w[q] * inv;
        if (a != 0.f) {
            const float4 x0 = __ldg(reinterpret_cast<const float4*>(po + (size_t)q * NBIG + o));
            const float4 x1 = __ldg(reinterpret_cast<const float4*>(po + (size_t)q * NBIG + o + 4));
            acc[0] += x0.x * a; acc[1] += x0.y * a;
            acc[2] += x0.z * a; acc[3] += x0.w * a;
            acc[4] += x1.x * a; acc[5] += x1.y * a;
            acc[6] += x1.z * a; acc[7] += x1.w * a;
        }
    }

    __half2 outv[4];
    outv[0] = __floats2half2_rn(acc[0], acc[1]);
    outv[1] = __floats2half2_rn(acc[2], acc[3]);
    outv[2] = __floats2half2_rn(acc[4], acc[5]);
    outv[3] = __floats2half2_rn(acc[6], acc[7]);
    *reinterpret_cast<uint4*>(Y + o) = *reinterpret_cast<uint4*>(outv);
}

// ---------------------------------------------------------------------------
// fused = sigmoid(g1) * yc + sigmoid(g2) * y  (fp16 in/out)
// ---------------------------------------------------------------------------
__global__ __launch_bounds__(256) void gate_fuse_kernel(
    const __half* __restrict__ g1, const __half* __restrict__ g2,
    const __half* __restrict__ y, const __half* __restrict__ yc,
    __half* __restrict__ f)
{
    const int i = blockIdx.x * 256 + threadIdx.x;
    const uint4 ua = reinterpret_cast<const uint4*>(g1)[i];
    const uint4 ub = reinterpret_cast<const uint4*>(g2)[i];
    const uint4 uy = reinterpret_cast<const uint4*>(y)[i];
    const uint4 uc = reinterpret_cast<const uint4*>(yc)[i];
    const __half2* ha = reinterpret_cast<const __half2*>(&ua);
    const __half2* hb = reinterpret_cast<const __half2*>(&ub);
    const __half2* hy = reinterpret_cast<const __half2*>(&uy);
    const __half2* hc = reinterpret_cast<const __half2*>(&uc);
    __half2 ho[4];
#pragma unroll
    for (int k = 0; k < 4; ++k) {
        const float2 a = __half22float2(ha[k]);
        const float2 bg = __half22float2(hb[k]);
        const float2 yv = __half22float2(hy[k]);
        const float2 yw = __half22float2(hc[k]);
        ho[k] = __floats2half2_rn(sigf(a.x) * yw.x + sigf(bg.x) * yv.x,
                                  sigf(a.y) * yw.y + sigf(bg.y) * yv.y);
    }
    reinterpret_cast<uint4*>(f)[i] = *reinterpret_cast<uint4*>(ho);
}

// ---------------------------------------------------------------------------
// Launch
// ---------------------------------------------------------------------------
extern "C" void kernel_launch(void* const* d_in, const int* in_sizes, int n_in,
                              void* d_out, int out_size)
{
    const float* x  = (const float*)d_in[0];
    const float* c  = (const float*)d_in[1];
    const int* pad  = (const int*)d_in[3];
    const float* Wq = (const float*)d_in[4];
    const float* bq = (const float*)d_in[5];
    const float* Wk = (const float*)d_in[6];
    const float* bk = (const float*)d_in[7];
    const float* Wv = (const float*)d_in[8];
    const float* bv = (const float*)d_in[9];
    const float* Wkc = (const float*)d_in[10];
    const float* bkc = (const float*)d_in[11];
    const float* Wvc = (const float*)d_in[12];
    const float* bvc = (const float*)d_in[13];
    const float* Wg1 = (const float*)d_in[14];
    const float* bg1 = (const float*)d_in[15];
    const float* Wg2 = (const float*)d_in[16];
    const float* bg2 = (const float*)d_in[17];
    const float* Wp = (const float*)d_in[18];
    const float* bp = (const float*)d_in[19];
    float* out = (float*)d_out;

    __half* H = nullptr;
    cudaGetSymbolAddress((void**)&H, g_h);
    float* PO = nullptr;
    cudaGetSymbolAddress((void**)&PO, g_po);
    float2* ML = nullptr;
    cudaGetSymbolAddress((void**)&ML, g_ml);

    __half* XH  = H + 0ULL * NBIG;
    __half* Qh  = H + 1ULL * NBIG;
    __half* Kh  = H + 2ULL * NBIG;
    __half* Vh  = H + 3ULL * NBIG;
    __half* Yh  = H + 4ULL * NBIG;
    __half* YCh = H + 5ULL * NBIG;
    __half* G1h = H + 6ULL * NBIG;
    __half* G2h = H + 7ULL * NBIG;
    __half* Fh  = H + 8ULL * NBIG;
    __half* CH  = H + 9ULL * NBIG;
    __half* KCh = CH + NSMALL;
    __half* VCh = CH + 2ULL * NSMALL;
    __half* WT  = CH + 3ULL * NSMALL;

    const int SMEM_AT = (128 * SAS + 128 * SAS + 128 * SAS + 128 * SAS) * 2; // 73728
    cudaFuncSetAttribute(attn_kernel,
                         cudaFuncAttributeMaxDynamicSharedMemorySize, SMEM_AT);

    prep_kernel<<<NCONV + 2048, 256>>>(x, c, Wq, Wk, Wv, Wkc, Wvc, Wg1, Wg2, Wp,
                                       XH, CH, WT);

    proj_kernel<<<400, 256>>>(XH, CH, WT, bq, bk, bv, bkc, bvc,
                              Qh, Kh, Vh, KCh, VCh);

    attn_kernel<<<dim3(80, BATCH * HEADS), 256, SMEM_AT>>>(
        Qh, Kh, Vh, KCh, VCh, pad, PO, ML, YCh);
    merge_kernel<<<BT * 64 / 256, 256>>>(PO, ML, Yh);

    gates_kernel<<<256, 256>>>(Yh, YCh, WT, bg1, bg2, G1h, G2h);
    gate_fuse_kernel<<<NBIG / 8 / 256, 256>>>(G1h, G2h, Yh, YCh, Fh);
    final_gemm_kernel<<<128, 256>>>(Fh, WT, bp, out);
}